// round 2
// baseline (speedup 1.0000x reference)
#include <cuda_runtime.h>
#include <math.h>
#include <stdint.h>

#define NPIX 4096
#define CDIM 256
#define NLOW 256
#define KLEN 32
#define NHEADS 8
#define HD 32
#define BATCH 2

// ---------------- scratch (no allocations allowed) ----------------
__device__ float g_q[BATCH * NPIX * CDIM];   // (B, N, C)
__device__ float g_k[BATCH * NPIX * CDIM];
__device__ float g_v[BATCH * NPIX * CDIM];
__device__ float g_x[BATCH * NPIX * CDIM];
__device__ int   g_idx[BATCH * NLOW * KLEN];

// ---------------- helpers ----------------
__device__ __forceinline__ uint32_t f2tf(float x) {
    uint32_t r;
    asm("cvt.rna.tf32.f32 %0, %1;" : "=r"(r) : "f"(x));
    return r;
}

__device__ __forceinline__ void mma_tf32(float* c, const uint32_t* a, const uint32_t* b) {
    asm volatile(
        "mma.sync.aligned.m16n8k8.row.col.f32.tf32.tf32.f32 "
        "{%0,%1,%2,%3},{%4,%5,%6,%7},{%8,%9},{%0,%1,%2,%3};"
        : "+f"(c[0]), "+f"(c[1]), "+f"(c[2]), "+f"(c[3])
        : "r"(a[0]), "r"(a[1]), "r"(a[2]), "r"(a[3]), "r"(b[0]), "r"(b[1]));
}

// ---------------- top-2 + index expansion ----------------
__global__ void topk_expand_kernel(const float* __restrict__ cmap,
                                   int* __restrict__ idx) {
    int b = blockIdx.x;
    int i = threadIdx.x;                       // 0..255
    const float* row = cmap + ((size_t)b * NLOW + i) * NLOW;
    float m1 = -1e30f, m2 = -1e30f;
    int i1 = 0, i2 = 0;
    for (int j = 0; j < NLOW; j++) {
        float v = row[j];
        if (v > m1)      { m2 = m1; i2 = i1; m1 = v; i1 = j; }
        else if (v > m2) { m2 = v;  i2 = j; }
    }
    int* orow = idx + ((size_t)b * NLOW + i) * KLEN;
    #pragma unroll
    for (int k = 0; k < 2; k++) {
        int t  = (k == 0) ? i1 : i2;
        int r0 = (t >> 4) << 2;
        int c0 = (t & 15) << 2;
        #pragma unroll
        for (int dr = 0; dr < 4; dr++)
            #pragma unroll
            for (int dc = 0; dc < 4; dc++)
                orow[k * 16 + dr * 4 + dc] = (r0 + dr) * 64 + (c0 + dc);
    }
}

// ---------------- tf32 tensor-core GEMM ----------------
// MODE 0 (projection): A is (C, NPIX) [m contiguous], computes out[m,c] = sum_k A[k,m]*W[k,c]+bias[c]
//                      out is (NPIX, C), c contiguous.
// MODE 1 (output):     A is (NPIX, C) [k contiguous], computes out[c,m] = sum_k A[m,k]*W[k,c]+bias[c]
//                      out is (C, NPIX), m contiguous (transposed store).
// CTA tile 128(m) x 64(c), K-chunk 32, 8 warps = 4(m) x 2(c), warp tile 32x32.
template<int MODE>
__global__ __launch_bounds__(256) void gemm_tf32(const float* __restrict__ A,
                                                 const float* __restrict__ W,
                                                 const float* __restrict__ bias,
                                                 float* __restrict__ out) {
    __shared__ uint32_t As[32][132];   // [k][m], padded
    __shared__ uint32_t Bs[32][68];    // [k][c], padded
    int b  = blockIdx.z;
    int m0 = blockIdx.x * 128;
    int c0 = blockIdx.y * 64;
    int t    = threadIdx.x;
    int lane = t & 31, w = t >> 5;
    int wm = w & 3, wc = w >> 2;
    int g = lane >> 2, tq = lane & 3;
    const float* Ab = A + (MODE == 0 ? (size_t)b * CDIM * NPIX : (size_t)b * NPIX * CDIM);

    float acc[2][4][4] = {};

    for (int k0 = 0; k0 < CDIM; k0 += 32) {
        if (MODE == 0) {
            #pragma unroll
            for (int i = 0; i < 4; i++) {
                int idx = i * 256 + t;
                int k = idx >> 5, m4 = idx & 31;
                float4 v = *(const float4*)&Ab[(size_t)(k0 + k) * NPIX + m0 + m4 * 4];
                uint32_t* d = &As[k][m4 * 4];
                d[0] = f2tf(v.x); d[1] = f2tf(v.y); d[2] = f2tf(v.z); d[3] = f2tf(v.w);
            }
        } else {
            #pragma unroll
            for (int i = 0; i < 4; i++) {
                int idx = i * 256 + t;
                int m = idx >> 3, kf = idx & 7;
                float4 v = *(const float4*)&Ab[(size_t)(m0 + m) * CDIM + k0 + kf * 4];
                As[kf * 4 + 0][m] = f2tf(v.x);
                As[kf * 4 + 1][m] = f2tf(v.y);
                As[kf * 4 + 2][m] = f2tf(v.z);
                As[kf * 4 + 3][m] = f2tf(v.w);
            }
        }
        #pragma unroll
        for (int i = 0; i < 2; i++) {
            int idx = i * 256 + t;
            int k = idx >> 4, c4 = idx & 15;
            float4 v = *(const float4*)&W[(size_t)(k0 + k) * CDIM + c0 + c4 * 4];
            uint32_t* d = &Bs[k][c4 * 4];
            d[0] = f2tf(v.x); d[1] = f2tf(v.y); d[2] = f2tf(v.z); d[3] = f2tf(v.w);
        }
        __syncthreads();

        #pragma unroll
        for (int kk = 0; kk < 32; kk += 8) {
            uint32_t a[2][4], bb[4][2];
            #pragma unroll
            for (int ms = 0; ms < 2; ms++) {
                int bm = wm * 32 + ms * 16;
                a[ms][0] = As[kk + tq][bm + g];
                a[ms][1] = As[kk + tq][bm + g + 8];
                a[ms][2] = As[kk + 4 + tq][bm + g];
                a[ms][3] = As[kk + 4 + tq][bm + g + 8];
            }
            #pragma unroll
            for (int cs = 0; cs < 4; cs++) {
                int bc = wc * 32 + cs * 8;
                bb[cs][0] = Bs[kk + tq][bc + g];
                bb[cs][1] = Bs[kk + 4 + tq][bc + g];
            }
            #pragma unroll
            for (int ms = 0; ms < 2; ms++)
                #pragma unroll
                for (int cs = 0; cs < 4; cs++)
                    mma_tf32(acc[ms][cs], a[ms], bb[cs]);
        }
        __syncthreads();
    }

    // epilogue
    #pragma unroll
    for (int ms = 0; ms < 2; ms++) {
        int mb = m0 + wm * 32 + ms * 16;
        #pragma unroll
        for (int cs = 0; cs < 4; cs++) {
            int c = c0 + wc * 32 + cs * 8 + tq * 2;
            float b0v = bias[c], b1v = bias[c + 1];
            int r0 = mb + g, r1 = mb + g + 8;
            if (MODE == 0) {
                float* o = out + (size_t)b * NPIX * CDIM;
                float2 v0 = {acc[ms][cs][0] + b0v, acc[ms][cs][1] + b1v};
                float2 v1 = {acc[ms][cs][2] + b0v, acc[ms][cs][3] + b1v};
                *(float2*)&o[(size_t)r0 * CDIM + c] = v0;
                *(float2*)&o[(size_t)r1 * CDIM + c] = v1;
            } else {
                float* o = out + (size_t)b * CDIM * NPIX;
                o[(size_t)c       * NPIX + r0] = acc[ms][cs][0] + b0v;
                o[(size_t)(c + 1) * NPIX + r0] = acc[ms][cs][1] + b1v;
                o[(size_t)c       * NPIX + r1] = acc[ms][cs][2] + b0v;
                o[(size_t)(c + 1) * NPIX + r1] = acc[ms][cs][3] + b1v;
            }
        }
    }
}

// ---------------- fused block sparse attention ----------------
// 16 consecutive queries share 32 gathered keys. CTA = (q_low, b), 256 threads:
// thread = (q[4b], h[3b], kk[1b]); kk = which half of the 32 keys.
// Softmax/output merged across the kk pair via shfl_xor(1).
__global__ __launch_bounds__(256) void attn_kernel(const float* __restrict__ qproj,
                                                   const float* __restrict__ kproj,
                                                   const float* __restrict__ vproj,
                                                   const int* __restrict__ idx,
                                                   float* __restrict__ x) {
    int qlow = blockIdx.x;
    int b    = blockIdx.y;
    extern __shared__ float sm[];
    float* Ks = sm;                // [32][256]
    float* Vs = sm + KLEN * CDIM;  // [32][256]
    __shared__ int sidx[KLEN];
    int t = threadIdx.x;
    if (t < KLEN) sidx[t] = idx[((size_t)b * NLOW + qlow) * KLEN + t];
    __syncthreads();

    const float4* kp4 = (const float4*)kproj;
    const float4* vp4 = (const float4*)vproj;
    float4* Ks4 = (float4*)Ks;
    float4* Vs4 = (float4*)Vs;
    #pragma unroll
    for (int c = 0; c < 8; c++) {
        int li = c * 256 + t;              // 0..2047
        int r  = li >> 6;
        int c4 = li & 63;
        size_t src = ((size_t)(b * NPIX + sidx[r])) * 64 + c4;
        Ks4[li] = kp4[src];
        Vs4[li] = vp4[src];
    }
    __syncthreads();

    int kk = t & 1;
    int h  = (t >> 1) & 7;
    int q  = t >> 4;
    int n  = qlow * 16 + q;

    float qreg[HD];
    const float4* qp4 = (const float4*)(qproj + ((size_t)(b * NPIX + n)) * CDIM + h * HD);
    #pragma unroll
    for (int d4 = 0; d4 < 8; d4++) {
        float4 v = qp4[d4];
        qreg[d4 * 4 + 0] = v.x; qreg[d4 * 4 + 1] = v.y;
        qreg[d4 * 4 + 2] = v.z; qreg[d4 * 4 + 3] = v.w;
    }

    const float scale = 0.17677669529663687f;  // 32^-0.5
    float s[16];
    #pragma unroll
    for (int j = 0; j < 16; j++) {
        int k = kk * 16 + j;
        const float4* kr = (const float4*)(Ks + k * CDIM + h * HD);
        float acc = 0.f;
        #pragma unroll
        for (int d4 = 0; d4 < 8; d4++) {
            float4 kv = kr[d4];
            acc += qreg[d4 * 4 + 0] * kv.x + qreg[d4 * 4 + 1] * kv.y
                 + qreg[d4 * 4 + 2] * kv.z + qreg[d4 * 4 + 3] * kv.w;
        }
        s[j] = acc * scale;
    }

    float mloc = s[0];
    #pragma unroll
    for (int j = 1; j < 16; j++) mloc = fmaxf(mloc, s[j]);
    float moth = __shfl_xor_sync(0xffffffffu, mloc, 1);
    float m = fmaxf(mloc, moth);

    float ssum = 0.f;
    #pragma unroll
    for (int j = 0; j < 16; j++) { s[j] = __expf(s[j] - m); ssum += s[j]; }

    float o[HD] = {};
    #pragma unroll
    for (int j = 0; j < 16; j++) {
        int k = kk * 16 + j;
        float p = s[j];
        const float4* vr = (const float4*)(Vs + k * CDIM + h * HD);
        #pragma unroll
        for (int d4 = 0; d4 < 8; d4++) {
            float4 vv = vr[d4];
            o[d4 * 4 + 0] += p * vv.x; o[d4 * 4 + 1] += p * vv.y;
            o[d4 * 4 + 2] += p * vv.z; o[d4 * 4 + 3] += p * vv.w;
        }
    }

    float stot = ssum + __shfl_xor_sync(0xffffffffu, ssum, 1);
    float inv = 1.f / stot;
    // merge partial outputs across the kk pair; each thread writes its 16 dims
    float od[16];
    #pragma unroll
    for (int d = 0; d < HD; d++) {
        float tot = o[d] + __shfl_xor_sync(0xffffffffu, o[d], 1);
        int base = kk * 16;
        if (d >= base && d < base + 16) od[d - base] = tot * inv;
    }
    float4* xo = (float4*)(x + ((size_t)(b * NPIX + n)) * CDIM + h * HD + kk * 16);
    #pragma unroll
    for (int d4 = 0; d4 < 4; d4++) {
        float4 r = {od[d4 * 4 + 0], od[d4 * 4 + 1], od[d4 * 4 + 2], od[d4 * 4 + 3]};
        xo[d4] = r;
    }
}

// ---------------- launch ----------------
extern "C" void kernel_launch(void* const* d_in, const int* in_sizes, int n_in,
                              void* d_out, int out_size) {
    const float* qh   = (const float*)d_in[0];
    const float* kh   = (const float*)d_in[1];
    const float* vh   = (const float*)d_in[2];
    const float* cmap = (const float*)d_in[3];
    const float* Wq   = (const float*)d_in[4];
    const float* bq   = (const float*)d_in[5];
    const float* Wk   = (const float*)d_in[6];
    const float* bk   = (const float*)d_in[7];
    const float* Wv   = (const float*)d_in[8];
    const float* bv   = (const float*)d_in[9];
    const float* Wo   = (const float*)d_in[10];
    const float* bo   = (const float*)d_in[11];
    float* out = (float*)d_out;

    float *pq, *pk, *pv, *px;
    int* pidx;
    cudaGetSymbolAddress((void**)&pq,   g_q);
    cudaGetSymbolAddress((void**)&pk,   g_k);
    cudaGetSymbolAddress((void**)&pv,   g_v);
    cudaGetSymbolAddress((void**)&px,   g_x);
    cudaGetSymbolAddress((void**)&pidx, g_idx);

    cudaFuncSetAttribute(attn_kernel, cudaFuncAttributeMaxDynamicSharedMemorySize, 65536);

    topk_expand_kernel<<<BATCH, NLOW>>>(cmap, pidx);

    dim3 gg(NPIX / 128, CDIM / 64, BATCH);
    gemm_tf32<0><<<gg, 256>>>(qh, Wq, bq, pq);
    gemm_tf32<0><<<gg, 256>>>(kh, Wk, bk, pk);
    gemm_tf32<0><<<gg, 256>>>(vh, Wv, bv, pv);

    attn_kernel<<<dim3(NLOW, BATCH), 256, 65536>>>(pq, pk, pv, pidx, px);

    gemm_tf32<1><<<gg, 256>>>(px, Wo, bo, out);
}

// round 3
// speedup vs baseline: 1.2397x; 1.2397x over previous
#include <cuda_runtime.h>
#include <math.h>
#include <stdint.h>

#define NPIX 4096
#define CDIM 256
#define NLOW 256
#define KLEN 32
#define NHEADS 8
#define HD 32
#define BATCH 2

// ---------------- scratch (no allocations allowed) ----------------
__device__ float g_q[BATCH * NPIX * CDIM];   // (B, N, C)
__device__ float g_k[BATCH * NPIX * CDIM];
__device__ float g_v[BATCH * NPIX * CDIM];
__device__ float g_x[BATCH * NPIX * CDIM];
__device__ int   g_idx[BATCH * NLOW * KLEN];

// ---------------- helpers ----------------
__device__ __forceinline__ uint32_t f2tf(float x) {
    uint32_t r;
    asm("cvt.rna.tf32.f32 %0, %1;" : "=r"(r) : "f"(x));
    return r;
}

__device__ __forceinline__ void mma_tf32(float* c, const uint32_t* a, const uint32_t* b) {
    asm volatile(
        "mma.sync.aligned.m16n8k8.row.col.f32.tf32.tf32.f32 "
        "{%0,%1,%2,%3},{%4,%5,%6,%7},{%8,%9},{%0,%1,%2,%3};"
        : "+f"(c[0]), "+f"(c[1]), "+f"(c[2]), "+f"(c[3])
        : "r"(a[0]), "r"(a[1]), "r"(a[2]), "r"(a[3]), "r"(b[0]), "r"(b[1]));
}

// ---------------- top-2 + index expansion (one warp per row) ----------------
__global__ __launch_bounds__(256) void topk_expand_kernel(const float* __restrict__ cmap,
                                                          int* __restrict__ idx) {
    int lane = threadIdx.x & 31;
    int row  = blockIdx.x * 8 + (threadIdx.x >> 5);   // 0..511
    const float* r = cmap + (size_t)row * NLOW;
    float m1 = -1e30f, m2 = -1e30f;
    int i1 = 0, i2 = 0;
    #pragma unroll
    for (int l = 0; l < 8; l++) {
        int j = l * 32 + lane;
        float v = r[j];
        if (v > m1)      { m2 = m1; i2 = i1; m1 = v; i1 = j; }
        else if (v > m2) { m2 = v;  i2 = j; }
    }
    #pragma unroll
    for (int off = 16; off > 0; off >>= 1) {
        float om1 = __shfl_xor_sync(0xffffffffu, m1, off);
        float om2 = __shfl_xor_sync(0xffffffffu, m2, off);
        int   oi1 = __shfl_xor_sync(0xffffffffu, i1, off);
        int   oi2 = __shfl_xor_sync(0xffffffffu, i2, off);
        if (om1 > m1) {
            if (m1 > om2) { m2 = m1; i2 = i1; } else { m2 = om2; i2 = oi2; }
            m1 = om1; i1 = oi1;
        } else if (om1 > m2) { m2 = om1; i2 = oi1; }
    }
    // all lanes agree; lane writes one of the 32 expanded indices
    int t   = (lane < 16) ? i1 : i2;
    int pos = lane & 15;
    int r0  = (t >> 4) << 2;
    int c0  = (t & 15) << 2;
    idx[(size_t)row * KLEN + lane] = (r0 + (pos >> 2)) * 64 + c0 + (pos & 3);
}

// ---------------- tf32 tensor-core GEMM, software-pipelined ----------------
// MODE 0 (fused QKV proj): grid.z = 6 (which*2+batch).
//   out[m=pixel][n=chan] = sum_k A[k][m] * W[k][n] + bias[n];  A is (C, NPIX) m-contig.
// MODE 1 (output proj):   grid.z = 2 (batch).
//   out[m=chan][n=pixel] = sum_k W[k][m] * X[n][k] + bias[m];  X is (NPIX, C) k-contig.
// CTA tile 128(m) x 64(n), K-chunk 32, 8 warps = 4(m) x 2(n), warp tile 32x32.
template<int MODE>
__global__ __launch_bounds__(256) void gemm_tf32(
    const float* __restrict__ Aq, const float* __restrict__ Ak, const float* __restrict__ Av,
    const float* __restrict__ Wq, const float* __restrict__ Wk, const float* __restrict__ Wv,
    const float* __restrict__ bq, const float* __restrict__ bk, const float* __restrict__ bv,
    float* __restrict__ oq, float* __restrict__ ok, float* __restrict__ ov) {
    __shared__ uint32_t As[32][132];   // [k][m], padded
    __shared__ uint32_t Bs[32][68];    // [k][n], padded
    int m0 = blockIdx.x * 128;
    int c0 = blockIdx.y * 64;
    int t    = threadIdx.x;
    int lane = t & 31, w = t >> 5;
    int wm = w & 3, wc = w >> 2;
    int g = lane >> 2, tq = lane & 3;

    const float* PA;  size_t SA;      // A operand: rows k, m contiguous
    const float* PB;                  // B operand base
    const float* bias;
    float* outp;  size_t OS;

    if (MODE == 0) {
        int which = blockIdx.z >> 1, b = blockIdx.z & 1;
        const float* Ain = (which == 0) ? Aq : (which == 1) ? Ak : Av;
        PA   = Ain + (size_t)b * CDIM * NPIX;  SA = NPIX;
        PB   = (which == 0) ? Wq : (which == 1) ? Wk : Wv;
        bias = (which == 0) ? bq : (which == 1) ? bk : bv;
        float* Out = (which == 0) ? oq : (which == 1) ? ok : ov;
        outp = Out + (size_t)b * NPIX * CDIM;  OS = CDIM;
    } else {
        int b = blockIdx.z;
        PA   = Wq;  SA = CDIM;                      // Wo, m = out-channel contiguous
        PB   = Aq + (size_t)b * NPIX * CDIM;        // X, k contiguous
        bias = bq;
        outp = oq + (size_t)b * CDIM * NPIX;  OS = NPIX;
    }

    float acc[2][4][4] = {};
    float4 pa[4], pb[2];

    // prologue global loads (k0 = 0)
    #pragma unroll
    for (int i = 0; i < 4; i++) {
        int idx = i * 256 + t;
        pa[i] = *(const float4*)&PA[(size_t)(idx >> 5) * SA + m0 + (idx & 31) * 4];
    }
    #pragma unroll
    for (int i = 0; i < 2; i++) {
        int idx = i * 256 + t;
        if (MODE == 0)
            pb[i] = *(const float4*)&PB[(size_t)(idx >> 4) * CDIM + c0 + (idx & 15) * 4];
        else
            pb[i] = *(const float4*)&PB[(size_t)(c0 + (idx >> 3)) * CDIM + (idx & 7) * 4];
    }

    for (int k0 = 0; k0 < CDIM; k0 += 32) {
        // stage regs -> smem (with tf32 convert)
        #pragma unroll
        for (int i = 0; i < 4; i++) {
            int idx = i * 256 + t;
            uint32_t* d = &As[idx >> 5][(idx & 31) * 4];
            d[0] = f2tf(pa[i].x); d[1] = f2tf(pa[i].y);
            d[2] = f2tf(pa[i].z); d[3] = f2tf(pa[i].w);
        }
        #pragma unroll
        for (int i = 0; i < 2; i++) {
            int idx = i * 256 + t;
            if (MODE == 0) {
                uint32_t* d = &Bs[idx >> 4][(idx & 15) * 4];
                d[0] = f2tf(pb[i].x); d[1] = f2tf(pb[i].y);
                d[2] = f2tf(pb[i].z); d[3] = f2tf(pb[i].w);
            } else {
                int n = idx >> 3, kf = (idx & 7) * 4;
                Bs[kf + 0][n] = f2tf(pb[i].x);
                Bs[kf + 1][n] = f2tf(pb[i].y);
                Bs[kf + 2][n] = f2tf(pb[i].z);
                Bs[kf + 3][n] = f2tf(pb[i].w);
            }
        }
        __syncthreads();

        // prefetch next K-chunk while MMAs run
        if (k0 + 32 < CDIM) {
            int kn = k0 + 32;
            #pragma unroll
            for (int i = 0; i < 4; i++) {
                int idx = i * 256 + t;
                pa[i] = *(const float4*)&PA[(size_t)(kn + (idx >> 5)) * SA + m0 + (idx & 31) * 4];
            }
            #pragma unroll
            for (int i = 0; i < 2; i++) {
                int idx = i * 256 + t;
                if (MODE == 0)
                    pb[i] = *(const float4*)&PB[(size_t)(kn + (idx >> 4)) * CDIM + c0 + (idx & 15) * 4];
                else
                    pb[i] = *(const float4*)&PB[(size_t)(c0 + (idx >> 3)) * CDIM + kn + (idx & 7) * 4];
            }
        }

        #pragma unroll
        for (int kk = 0; kk < 32; kk += 8) {
            uint32_t a[2][4], bb[4][2];
            #pragma unroll
            for (int ms = 0; ms < 2; ms++) {
                int bm = wm * 32 + ms * 16;
                a[ms][0] = As[kk + tq][bm + g];
                a[ms][1] = As[kk + tq][bm + g + 8];
                a[ms][2] = As[kk + 4 + tq][bm + g];
                a[ms][3] = As[kk + 4 + tq][bm + g + 8];
            }
            #pragma unroll
            for (int cs = 0; cs < 4; cs++) {
                int bc = wc * 32 + cs * 8;
                bb[cs][0] = Bs[kk + tq][bc + g];
                bb[cs][1] = Bs[kk + 4 + tq][bc + g];
            }
            #pragma unroll
            for (int ms = 0; ms < 2; ms++)
                #pragma unroll
                for (int cs = 0; cs < 4; cs++)
                    mma_tf32(acc[ms][cs], a[ms], bb[cs]);
        }
        __syncthreads();
    }

    // epilogue: n-contiguous float2 stores in both modes
    #pragma unroll
    for (int ms = 0; ms < 2; ms++) {
        int mb = m0 + wm * 32 + ms * 16;
        int r0 = mb + g, r1 = mb + g + 8;
        #pragma unroll
        for (int cs = 0; cs < 4; cs++) {
            int c = c0 + wc * 32 + cs * 8 + tq * 2;
            if (MODE == 0) {
                float2 b2 = *(const float2*)&bias[c];
                float2 v0 = {acc[ms][cs][0] + b2.x, acc[ms][cs][1] + b2.y};
                float2 v1 = {acc[ms][cs][2] + b2.x, acc[ms][cs][3] + b2.y};
                *(float2*)&outp[(size_t)r0 * OS + c] = v0;
                *(float2*)&outp[(size_t)r1 * OS + c] = v1;
            } else {
                float br0 = bias[r0], br1 = bias[r1];
                float2 v0 = {acc[ms][cs][0] + br0, acc[ms][cs][1] + br0};
                float2 v1 = {acc[ms][cs][2] + br1, acc[ms][cs][3] + br1};
                *(float2*)&outp[(size_t)r0 * OS + c] = v0;
                *(float2*)&outp[(size_t)r1 * OS + c] = v1;
            }
        }
    }
}

// ---------------- fused block sparse attention ----------------
// 16 consecutive queries share 32 gathered keys. CTA = (q_low, b), 256 threads:
// thread = (q[4b], h[3b], kk[1b]); kk = half of the 32 keys. Merge via shfl_xor(1).
__global__ __launch_bounds__(256) void attn_kernel(const float* __restrict__ qproj,
                                                   const float* __restrict__ kproj,
                                                   const float* __restrict__ vproj,
                                                   const int* __restrict__ idx,
                                                   float* __restrict__ x) {
    int qlow = blockIdx.x;
    int b    = blockIdx.y;
    extern __shared__ float sm[];
    float* Ks = sm;                // [32][256]
    float* Vs = sm + KLEN * CDIM;  // [32][256]
    __shared__ int sidx[KLEN];
    int t = threadIdx.x;
    if (t < KLEN) sidx[t] = idx[((size_t)b * NLOW + qlow) * KLEN + t];
    __syncthreads();

    const float4* kp4 = (const float4*)kproj;
    const float4* vp4 = (const float4*)vproj;
    float4* Ks4 = (float4*)Ks;
    float4* Vs4 = (float4*)Vs;
    #pragma unroll
    for (int c = 0; c < 8; c++) {
        int li = c * 256 + t;              // 0..2047
        int r  = li >> 6;
        int c4 = li & 63;
        size_t src = ((size_t)(b * NPIX + sidx[r])) * 64 + c4;
        Ks4[li] = kp4[src];
        Vs4[li] = vp4[src];
    }
    __syncthreads();

    int kk = t & 1;
    int h  = (t >> 1) & 7;
    int q  = t >> 4;
    int n  = qlow * 16 + q;

    float qreg[HD];
    const float4* qp4 = (const float4*)(qproj + ((size_t)(b * NPIX + n)) * CDIM + h * HD);
    #pragma unroll
    for (int d4 = 0; d4 < 8; d4++) {
        float4 v = qp4[d4];
        qreg[d4 * 4 + 0] = v.x; qreg[d4 * 4 + 1] = v.y;
        qreg[d4 * 4 + 2] = v.z; qreg[d4 * 4 + 3] = v.w;
    }

    const float scale = 0.17677669529663687f;  // 32^-0.5
    float s[16];
    #pragma unroll
    for (int j = 0; j < 16; j++) {
        int k = kk * 16 + j;
        const float4* kr = (const float4*)(Ks + k * CDIM + h * HD);
        float acc = 0.f;
        #pragma unroll
        for (int d4 = 0; d4 < 8; d4++) {
            float4 kv = kr[d4];
            acc += qreg[d4 * 4 + 0] * kv.x + qreg[d4 * 4 + 1] * kv.y
                 + qreg[d4 * 4 + 2] * kv.z + qreg[d4 * 4 + 3] * kv.w;
        }
        s[j] = acc * scale;
    }

    float mloc = s[0];
    #pragma unroll
    for (int j = 1; j < 16; j++) mloc = fmaxf(mloc, s[j]);
    float m = fmaxf(mloc, __shfl_xor_sync(0xffffffffu, mloc, 1));

    float ssum = 0.f;
    #pragma unroll
    for (int j = 0; j < 16; j++) { s[j] = __expf(s[j] - m); ssum += s[j]; }

    float o[HD] = {};
    #pragma unroll
    for (int j = 0; j < 16; j++) {
        int k = kk * 16 + j;
        float p = s[j];
        const float4* vr = (const float4*)(Vs + k * CDIM + h * HD);
        #pragma unroll
        for (int d4 = 0; d4 < 8; d4++) {
            float4 vv = vr[d4];
            o[d4 * 4 + 0] += p * vv.x; o[d4 * 4 + 1] += p * vv.y;
            o[d4 * 4 + 2] += p * vv.z; o[d4 * 4 + 3] += p * vv.w;
        }
    }

    float stot = ssum + __shfl_xor_sync(0xffffffffu, ssum, 1);
    float inv = 1.f / stot;

    // merge partials across the kk pair — all indices compile-time (no spills)
    float od[16];
    #pragma unroll
    for (int j = 0; j < 16; j++) {
        float t0 = o[j]      + __shfl_xor_sync(0xffffffffu, o[j],      1);
        float t1 = o[j + 16] + __shfl_xor_sync(0xffffffffu, o[j + 16], 1);
        od[j] = (kk ? t1 : t0) * inv;
    }
    float4* xo = (float4*)(x + ((size_t)(b * NPIX + n)) * CDIM + h * HD + kk * 16);
    #pragma unroll
    for (int d4 = 0; d4 < 4; d4++) {
        float4 r = {od[d4 * 4 + 0], od[d4 * 4 + 1], od[d4 * 4 + 2], od[d4 * 4 + 3]};
        xo[d4] = r;
    }
}

// ---------------- launch ----------------
extern "C" void kernel_launch(void* const* d_in, const int* in_sizes, int n_in,
                              void* d_out, int out_size) {
    const float* qh   = (const float*)d_in[0];
    const float* kh   = (const float*)d_in[1];
    const float* vh   = (const float*)d_in[2];
    const float* cmap = (const float*)d_in[3];
    const float* Wq   = (const float*)d_in[4];
    const float* bq   = (const float*)d_in[5];
    const float* Wk   = (const float*)d_in[6];
    const float* bk   = (const float*)d_in[7];
    const float* Wv   = (const float*)d_in[8];
    const float* bv   = (const float*)d_in[9];
    const float* Wo   = (const float*)d_in[10];
    const float* bo   = (const float*)d_in[11];
    float* out = (float*)d_out;

    float *pq, *pk, *pv, *px;
    int* pidx;
    cudaGetSymbolAddress((void**)&pq,   g_q);
    cudaGetSymbolAddress((void**)&pk,   g_k);
    cudaGetSymbolAddress((void**)&pv,   g_v);
    cudaGetSymbolAddress((void**)&px,   g_x);
    cudaGetSymbolAddress((void**)&pidx, g_idx);

    cudaFuncSetAttribute(attn_kernel, cudaFuncAttributeMaxDynamicSharedMemorySize, 65536);

    topk_expand_kernel<<<64, 256>>>(cmap, pidx);

    // fused Q/K/V projections: one launch, grid.z = which*2 + batch
    dim3 gp(NPIX / 128, CDIM / 64, 6);
    gemm_tf32<0><<<gp, 256>>>(qh, kh, vh, Wq, Wk, Wv, bq, bk, bv, pq, pk, pv);

    attn_kernel<<<dim3(NLOW, BATCH), 256, 65536>>>(pq, pk, pv, pidx, px);

    // output projection: out (B, C, NPIX)
    dim3 go(CDIM / 128, NPIX / 64, BATCH);
    gemm_tf32<1><<<go, 256>>>(px, nullptr, nullptr, Wo, nullptr, nullptr,
                              bo, nullptr, nullptr, out, nullptr, nullptr);
}

// round 4
// speedup vs baseline: 2.3309x; 1.8802x over previous
#include <cuda_runtime.h>
#include <math.h>
#include <stdint.h>

#define NPIX 4096
#define CDIM 256
#define NLOW 256
#define KLEN 32
#define NHEADS 8
#define HD 32
#define BATCH 2

// ---------------- scratch (no allocations allowed) ----------------
__device__ float g_q[BATCH * NPIX * CDIM];   // (B, N, C)
__device__ float g_k[BATCH * NPIX * CDIM];
__device__ float g_v[BATCH * NPIX * CDIM];
__device__ float g_x[BATCH * NPIX * CDIM];
__device__ int   g_idx[BATCH * NLOW * KLEN];

// ---------------- helpers ----------------
__device__ __forceinline__ uint32_t f2tf(float x) {
    uint32_t r;
    asm("cvt.rna.tf32.f32 %0, %1;" : "=r"(r) : "f"(x));
    return r;
}

__device__ __forceinline__ void mma_tf32(float* c, const uint32_t* a, const uint32_t* b) {
    asm volatile(
        "mma.sync.aligned.m16n8k8.row.col.f32.tf32.tf32.f32 "
        "{%0,%1,%2,%3},{%4,%5,%6,%7},{%8,%9},{%0,%1,%2,%3};"
        : "+f"(c[0]), "+f"(c[1]), "+f"(c[2]), "+f"(c[3])
        : "r"(a[0]), "r"(a[1]), "r"(a[2]), "r"(a[3]), "r"(b[0]), "r"(b[1]));
}

// ---------------- top-2 + index expansion (one warp per row) ----------------
__global__ __launch_bounds__(256) void topk_expand_kernel(const float* __restrict__ cmap,
                                                          int* __restrict__ idx) {
    int lane = threadIdx.x & 31;
    int row  = blockIdx.x * 8 + (threadIdx.x >> 5);   // 0..511
    const float* r = cmap + (size_t)row * NLOW;
    float m1 = -1e30f, m2 = -1e30f;
    int i1 = 0, i2 = 0;
    #pragma unroll
    for (int l = 0; l < 8; l++) {
        int j = l * 32 + lane;
        float v = r[j];
        if (v > m1)      { m2 = m1; i2 = i1; m1 = v; i1 = j; }
        else if (v > m2) { m2 = v;  i2 = j; }
    }
    #pragma unroll
    for (int off = 16; off > 0; off >>= 1) {
        float om1 = __shfl_xor_sync(0xffffffffu, m1, off);
        float om2 = __shfl_xor_sync(0xffffffffu, m2, off);
        int   oi1 = __shfl_xor_sync(0xffffffffu, i1, off);
        int   oi2 = __shfl_xor_sync(0xffffffffu, i2, off);
        if (om1 > m1) {
            if (m1 > om2) { m2 = m1; i2 = i1; } else { m2 = om2; i2 = oi2; }
            m1 = om1; i1 = oi1;
        } else if (om1 > m2) { m2 = om1; i2 = oi1; }
    }
    int t   = (lane < 16) ? i1 : i2;
    int pos = lane & 15;
    int r0  = (t >> 4) << 2;
    int c0  = (t & 15) << 2;
    idx[(size_t)row * KLEN + lane] = (r0 + (pos >> 2)) * 64 + c0 + (pos & 3);
}

// ---------------- tf32 tensor-core GEMM, double-buffered ----------------
// MODE 0 (fused QKV proj): grid.z = 6 (which*2+batch).
// MODE 1 (output proj):    grid.z = 2 (batch); M-dim = out-channels, N-dim = pixels.
// CTA tile 128(m) x 64(n), K-chunk 32, 8 warps = 4(m) x 2(n), warp tile 32x32.
template<int MODE>
__global__ __launch_bounds__(256) void gemm_tf32(
    const float* __restrict__ Aq, const float* __restrict__ Ak, const float* __restrict__ Av,
    const float* __restrict__ Wq, const float* __restrict__ Wk, const float* __restrict__ Wv,
    const float* __restrict__ bq, const float* __restrict__ bk, const float* __restrict__ bv,
    float* __restrict__ oq, float* __restrict__ ok, float* __restrict__ ov) {
    __shared__ uint32_t As[2][32][132];   // [stage][k][m], padded
    __shared__ uint32_t Bs[2][32][68];    // [stage][k][n], padded
    int m0 = blockIdx.x * 128;
    int c0 = blockIdx.y * 64;
    int t    = threadIdx.x;
    int lane = t & 31, w = t >> 5;
    int wm = w & 3, wc = w >> 2;
    int g = lane >> 2, tq = lane & 3;

    const float* PA;  size_t SA;
    const float* PB;
    const float* bias;
    float* outp;  size_t OS;

    if (MODE == 0) {
        int which = blockIdx.z >> 1, b = blockIdx.z & 1;
        const float* Ain = (which == 0) ? Aq : (which == 1) ? Ak : Av;
        PA   = Ain + (size_t)b * CDIM * NPIX;  SA = NPIX;
        PB   = (which == 0) ? Wq : (which == 1) ? Wk : Wv;
        bias = (which == 0) ? bq : (which == 1) ? bk : bv;
        float* Out = (which == 0) ? oq : (which == 1) ? ok : ov;
        outp = Out + (size_t)b * NPIX * CDIM;  OS = CDIM;
    } else {
        int b = blockIdx.z;
        PA   = Wq;  SA = CDIM;                      // Wo: m = out-channel
        PB   = Aq + (size_t)b * NPIX * CDIM;        // X: k contiguous
        bias = bq;
        outp = oq + (size_t)b * CDIM * NPIX;  OS = NPIX;
    }

    float acc[2][4][4] = {};
    float4 pa[4], pb[2];

    auto loadA = [&](int kb) {
        #pragma unroll
        for (int i = 0; i < 4; i++) {
            int idx = i * 256 + t;
            pa[i] = *(const float4*)&PA[(size_t)(kb + (idx >> 5)) * SA + m0 + (idx & 31) * 4];
        }
        #pragma unroll
        for (int i = 0; i < 2; i++) {
            int idx = i * 256 + t;
            if (MODE == 0)
                pb[i] = *(const float4*)&PB[(size_t)(kb + (idx >> 4)) * CDIM + c0 + (idx & 15) * 4];
            else
                pb[i] = *(const float4*)&PB[(size_t)(c0 + (idx >> 3)) * CDIM + kb + (idx & 7) * 4];
        }
    };
    auto storeS = [&](int s) {
        #pragma unroll
        for (int i = 0; i < 4; i++) {
            int idx = i * 256 + t;
            uint32_t* d = &As[s][idx >> 5][(idx & 31) * 4];
            d[0] = f2tf(pa[i].x); d[1] = f2tf(pa[i].y);
            d[2] = f2tf(pa[i].z); d[3] = f2tf(pa[i].w);
        }
        #pragma unroll
        for (int i = 0; i < 2; i++) {
            int idx = i * 256 + t;
            if (MODE == 0) {
                uint32_t* d = &Bs[s][idx >> 4][(idx & 15) * 4];
                d[0] = f2tf(pb[i].x); d[1] = f2tf(pb[i].y);
                d[2] = f2tf(pb[i].z); d[3] = f2tf(pb[i].w);
            } else {
                int n = idx >> 3, kf = (idx & 7) * 4;
                Bs[s][kf + 0][n] = f2tf(pb[i].x);
                Bs[s][kf + 1][n] = f2tf(pb[i].y);
                Bs[s][kf + 2][n] = f2tf(pb[i].z);
                Bs[s][kf + 3][n] = f2tf(pb[i].w);
            }
        }
    };

    loadA(0);
    storeS(0);
    __syncthreads();

    int s = 0;
    for (int k0 = 0; k0 < CDIM; k0 += 32, s ^= 1) {
        bool more = (k0 + 32 < CDIM);
        if (more) loadA(k0 + 32);   // global prefetch overlaps MMA below

        #pragma unroll
        for (int kk = 0; kk < 32; kk += 8) {
            uint32_t a[2][4], bb[4][2];
            #pragma unroll
            for (int ms = 0; ms < 2; ms++) {
                int bm = wm * 32 + ms * 16;
                a[ms][0] = As[s][kk + tq][bm + g];
                a[ms][1] = As[s][kk + tq][bm + g + 8];
                a[ms][2] = As[s][kk + 4 + tq][bm + g];
                a[ms][3] = As[s][kk + 4 + tq][bm + g + 8];
            }
            #pragma unroll
            for (int cs = 0; cs < 4; cs++) {
                int bc = wc * 32 + cs * 8;
                bb[cs][0] = Bs[s][kk + tq][bc + g];
                bb[cs][1] = Bs[s][kk + 4 + tq][bc + g];
            }
            #pragma unroll
            for (int ms = 0; ms < 2; ms++)
                #pragma unroll
                for (int cs = 0; cs < 4; cs++)
                    mma_tf32(acc[ms][cs], a[ms], bb[cs]);
        }
        if (more) {
            storeS(s ^ 1);
            __syncthreads();
        }
    }

    #pragma unroll
    for (int ms = 0; ms < 2; ms++) {
        int mb = m0 + wm * 32 + ms * 16;
        int r0 = mb + g, r1 = mb + g + 8;
        #pragma unroll
        for (int cs = 0; cs < 4; cs++) {
            int c = c0 + wc * 32 + cs * 8 + tq * 2;
            if (MODE == 0) {
                float2 b2 = *(const float2*)&bias[c];
                float2 v0 = {acc[ms][cs][0] + b2.x, acc[ms][cs][1] + b2.y};
                float2 v1 = {acc[ms][cs][2] + b2.x, acc[ms][cs][3] + b2.y};
                *(float2*)&outp[(size_t)r0 * OS + c] = v0;
                *(float2*)&outp[(size_t)r1 * OS + c] = v1;
            } else {
                float br0 = bias[r0], br1 = bias[r1];
                float2 v0 = {acc[ms][cs][0] + br0, acc[ms][cs][1] + br0};
                float2 v1 = {acc[ms][cs][2] + br1, acc[ms][cs][3] + br1};
                *(float2*)&outp[(size_t)r0 * OS + c] = v0;
                *(float2*)&outp[(size_t)r1 * OS + c] = v1;
            }
        }
    }
}

// ---------------- fused block sparse attention (bank-conflict-free) ----------------
// 16 consecutive queries share 32 gathered keys. CTA = (q_low, b), 256 threads:
// thread = (q[4b], h[3b], kk[1b]). K/V tiles stored with per-row XOR swizzle:
//   float4 column c4 -> c4 ^ ((c4>>3)&7)
// so reads at (h, d4) hit bank-group (d4^h): conflict-free across heads.
__global__ __launch_bounds__(256) void attn_kernel(const float* __restrict__ qproj,
                                                   const float* __restrict__ kproj,
                                                   const float* __restrict__ vproj,
                                                   const int* __restrict__ idx,
                                                   float* __restrict__ x) {
    int qlow = blockIdx.x;
    int b    = blockIdx.y;
    extern __shared__ float sm[];
    float4* Ks4 = (float4*)sm;                       // [32][64] float4, swizzled
    float4* Vs4 = (float4*)(sm + KLEN * CDIM);
    __shared__ int sidx[KLEN];
    int t = threadIdx.x;
    if (t < KLEN) sidx[t] = idx[((size_t)b * NLOW + qlow) * KLEN + t];
    __syncthreads();

    const float4* kp4 = (const float4*)kproj;
    const float4* vp4 = (const float4*)vproj;
    #pragma unroll
    for (int c = 0; c < 8; c++) {
        int li = c * 256 + t;              // 0..2047
        int r  = li >> 6;
        int c4 = li & 63;
        int dc = c4 ^ ((c4 >> 3) & 7);     // swizzled column
        size_t src = ((size_t)(b * NPIX + sidx[r])) * 64 + c4;
        Ks4[r * 64 + dc] = kp4[src];
        Vs4[r * 64 + dc] = vp4[src];
    }
    __syncthreads();

    int kk = t & 1;
    int h  = (t >> 1) & 7;
    int q  = t >> 4;
    int n  = qlow * 16 + q;

    float qreg[HD];
    const float4* qp4 = (const float4*)(qproj + ((size_t)(b * NPIX + n)) * CDIM + h * HD);
    #pragma unroll
    for (int d4 = 0; d4 < 8; d4++) {
        float4 v = qp4[d4];
        qreg[d4 * 4 + 0] = v.x; qreg[d4 * 4 + 1] = v.y;
        qreg[d4 * 4 + 2] = v.z; qreg[d4 * 4 + 3] = v.w;
    }

    const float scale = 0.17677669529663687f;  // 32^-0.5
    float s[16];
    #pragma unroll
    for (int j = 0; j < 16; j++) {
        int k = kk * 16 + j;
        const float4* kr = Ks4 + k * 64 + h * 8;
        float acc = 0.f;
        #pragma unroll
        for (int d4 = 0; d4 < 8; d4++) {
            float4 kv = kr[d4 ^ h];
            acc += qreg[d4 * 4 + 0] * kv.x + qreg[d4 * 4 + 1] * kv.y
                 + qreg[d4 * 4 + 2] * kv.z + qreg[d4 * 4 + 3] * kv.w;
        }
        s[j] = acc * scale;
    }

    float mloc = s[0];
    #pragma unroll
    for (int j = 1; j < 16; j++) mloc = fmaxf(mloc, s[j]);
    float m = fmaxf(mloc, __shfl_xor_sync(0xffffffffu, mloc, 1));

    float ssum = 0.f;
    #pragma unroll
    for (int j = 0; j < 16; j++) { s[j] = __expf(s[j] - m); ssum += s[j]; }

    float o[HD] = {};
    #pragma unroll
    for (int j = 0; j < 16; j++) {
        int k = kk * 16 + j;
        float p = s[j];
        const float4* vr = Vs4 + k * 64 + h * 8;
        #pragma unroll
        for (int d4 = 0; d4 < 8; d4++) {
            float4 vv = vr[d4 ^ h];
            o[d4 * 4 + 0] += p * vv.x; o[d4 * 4 + 1] += p * vv.y;
            o[d4 * 4 + 2] += p * vv.z; o[d4 * 4 + 3] += p * vv.w;
        }
    }

    float stot = ssum + __shfl_xor_sync(0xffffffffu, ssum, 1);
    float inv = 1.f / stot;

    float od[16];
    #pragma unroll
    for (int j = 0; j < 16; j++) {
        float t0 = o[j]      + __shfl_xor_sync(0xffffffffu, o[j],      1);
        float t1 = o[j + 16] + __shfl_xor_sync(0xffffffffu, o[j + 16], 1);
        od[j] = (kk ? t1 : t0) * inv;
    }
    float4* xo = (float4*)(x + ((size_t)(b * NPIX + n)) * CDIM + h * HD + kk * 16);
    #pragma unroll
    for (int d4 = 0; d4 < 4; d4++) {
        float4 r = {od[d4 * 4 + 0], od[d4 * 4 + 1], od[d4 * 4 + 2], od[d4 * 4 + 3]};
        xo[d4] = r;
    }
}

// ---------------- launch ----------------
extern "C" void kernel_launch(void* const* d_in, const int* in_sizes, int n_in,
                              void* d_out, int out_size) {
    const float* qh   = (const float*)d_in[0];
    const float* kh   = (const float*)d_in[1];
    const float* vh   = (const float*)d_in[2];
    const float* cmap = (const float*)d_in[3];
    const float* Wq   = (const float*)d_in[4];
    const float* bq   = (const float*)d_in[5];
    const float* Wk   = (const float*)d_in[6];
    const float* bk   = (const float*)d_in[7];
    const float* Wv   = (const float*)d_in[8];
    const float* bv   = (const float*)d_in[9];
    const float* Wo   = (const float*)d_in[10];
    const float* bo   = (const float*)d_in[11];
    float* out = (float*)d_out;

    float *pq, *pk, *pv, *px;
    int* pidx;
    cudaGetSymbolAddress((void**)&pq,   g_q);
    cudaGetSymbolAddress((void**)&pk,   g_k);
    cudaGetSymbolAddress((void**)&pv,   g_v);
    cudaGetSymbolAddress((void**)&px,   g_x);
    cudaGetSymbolAddress((void**)&pidx, g_idx);

    cudaFuncSetAttribute(attn_kernel, cudaFuncAttributeMaxDynamicSharedMemorySize, 65536);

    topk_expand_kernel<<<64, 256>>>(cmap, pidx);

    dim3 gp(NPIX / 128, CDIM / 64, 6);
    gemm_tf32<0><<<gp, 256>>>(qh, kh, vh, Wq, Wk, Wv, bq, bk, bv, pq, pk, pv);

    attn_kernel<<<dim3(NLOW, BATCH), 256, 65536>>>(pq, pk, pv, pidx, px);

    dim3 go(CDIM / 128, NPIX / 64, BATCH);
    gemm_tf32<1><<<go, 256>>>(px, nullptr, nullptr, Wo, nullptr, nullptr,
                              bo, nullptr, nullptr, out, nullptr, nullptr);
}

// round 5
// speedup vs baseline: 2.5536x; 1.0956x over previous
#include <cuda_runtime.h>
#include <math.h>
#include <stdint.h>

#define NPIX 4096
#define CDIM 256
#define NLOW 256
#define KLEN 32
#define NHEADS 8
#define HD 32
#define BATCH 2

// ---------------- scratch (no allocations allowed) ----------------
__device__ float g_q[BATCH * NPIX * CDIM];   // (B, N, C)
__device__ float g_k[BATCH * NPIX * CDIM];
__device__ float g_v[BATCH * NPIX * CDIM];
__device__ float g_x[BATCH * NPIX * CDIM];
__device__ int   g_idx[BATCH * NLOW * KLEN];

// ---------------- helpers ----------------
__device__ __forceinline__ uint32_t f2tf(float x) {
    uint32_t r;
    asm("cvt.rna.tf32.f32 %0, %1;" : "=r"(r) : "f"(x));
    return r;
}

__device__ __forceinline__ void mma_tf32(float* c, const uint32_t* a, const uint32_t* b) {
    asm volatile(
        "mma.sync.aligned.m16n8k8.row.col.f32.tf32.tf32.f32 "
        "{%0,%1,%2,%3},{%4,%5,%6,%7},{%8,%9},{%0,%1,%2,%3};"
        : "+f"(c[0]), "+f"(c[1]), "+f"(c[2]), "+f"(c[3])
        : "r"(a[0]), "r"(a[1]), "r"(a[2]), "r"(a[3]), "r"(b[0]), "r"(b[1]));
}

__device__ __forceinline__ void cp16(float* dst, const float* src) {
    uint32_t d = (uint32_t)__cvta_generic_to_shared(dst);
    asm volatile("cp.async.cg.shared.global [%0], [%1], 16;" :: "r"(d), "l"(src));
}
#define CP_COMMIT() asm volatile("cp.async.commit_group;" ::: "memory")
#define CP_WAIT1()  asm volatile("cp.async.wait_group 1;" ::: "memory")

// ---------------- top-2 + index expansion (one warp per row) ----------------
__global__ __launch_bounds__(256) void topk_expand_kernel(const float* __restrict__ cmap,
                                                          int* __restrict__ idx) {
    int lane = threadIdx.x & 31;
    int row  = blockIdx.x * 8 + (threadIdx.x >> 5);   // 0..511
    const float* r = cmap + (size_t)row * NLOW;
    float m1 = -1e30f, m2 = -1e30f;
    int i1 = 0, i2 = 0;
    #pragma unroll
    for (int l = 0; l < 8; l++) {
        int j = l * 32 + lane;
        float v = r[j];
        if (v > m1)      { m2 = m1; i2 = i1; m1 = v; i1 = j; }
        else if (v > m2) { m2 = v;  i2 = j; }
    }
    #pragma unroll
    for (int off = 16; off > 0; off >>= 1) {
        float om1 = __shfl_xor_sync(0xffffffffu, m1, off);
        float om2 = __shfl_xor_sync(0xffffffffu, m2, off);
        int   oi1 = __shfl_xor_sync(0xffffffffu, i1, off);
        int   oi2 = __shfl_xor_sync(0xffffffffu, i2, off);
        if (om1 > m1) {
            if (m1 > om2) { m2 = m1; i2 = i1; } else { m2 = om2; i2 = oi2; }
            m1 = om1; i1 = oi1;
        } else if (om1 > m2) { m2 = om1; i2 = oi1; }
    }
    int t   = (lane < 16) ? i1 : i2;
    int pos = lane & 15;
    int r0  = (t >> 4) << 2;
    int c0  = (t & 15) << 2;
    idx[(size_t)row * KLEN + lane] = (r0 + (pos >> 2)) * 64 + c0 + (pos & 3);
}

// ---------------- tf32 GEMM: 64x64 CTA tile, 3-stage cp.async pipeline ----------------
// MODE 0 (fused QKV proj): grid (64, 4, 6); A (C,NPIX) m-contig, W k-major, out (NPIX,C).
// MODE 1 (output proj):    grid (4, 64, 2); A = Wo (m=out-chan contig), B = X (k contig),
//                          out (C, NPIX) n-contiguous stores.
// 8 warps = 2(m) x 4(n); warp tile 32(m) x 16(n); K-chunk 32.
// smem per stage: A [32][72] + B ([32][72] k-major | [64][36] n-major) = 4608 floats.
#define STG 4608
template<int MODE>
__global__ __launch_bounds__(256) void gemm_tf32(
    const float* __restrict__ Aq, const float* __restrict__ Ak, const float* __restrict__ Av,
    const float* __restrict__ Wq, const float* __restrict__ Wk, const float* __restrict__ Wv,
    const float* __restrict__ bq, const float* __restrict__ bk, const float* __restrict__ bv,
    float* __restrict__ oq, float* __restrict__ ok, float* __restrict__ ov) {
    extern __shared__ float smem[];
    int m0 = blockIdx.x * 64;
    int c0 = blockIdx.y * 64;
    int t    = threadIdx.x;
    int lane = t & 31, w = t >> 5;
    int wm = w & 1, wc = w >> 1;
    int g = lane >> 2, tq = lane & 3;

    const float* PA;  size_t SA;
    const float* PB;
    const float* bias;
    float* outp;  size_t OS;

    if (MODE == 0) {
        int which = blockIdx.z >> 1, b = blockIdx.z & 1;
        const float* Ain = (which == 0) ? Aq : (which == 1) ? Ak : Av;
        PA   = Ain + (size_t)b * CDIM * NPIX;  SA = NPIX;
        PB   = (which == 0) ? Wq : (which == 1) ? Wk : Wv;
        bias = (which == 0) ? bq : (which == 1) ? bk : bv;
        float* Out = (which == 0) ? oq : (which == 1) ? ok : ov;
        outp = Out + (size_t)b * NPIX * CDIM;  OS = CDIM;
    } else {
        int b = blockIdx.z;
        PA   = Wq;  SA = CDIM;                      // Wo: m = out-channel contiguous
        PB   = Aq + (size_t)b * NPIX * CDIM;        // X: k contiguous
        bias = bq;
        outp = oq + (size_t)b * CDIM * NPIX;  OS = NPIX;
    }

    auto issue = [&](int st, int kb) {
        float* Abase = smem + st * STG;
        float* Bbase = Abase + 32 * 72;
        #pragma unroll
        for (int i = 0; i < 2; i++) {
            int idx = i * 256 + t;
            int row = idx >> 4, cc = (idx & 15) * 4;
            cp16(&Abase[row * 72 + cc], &PA[(size_t)(kb + row) * SA + m0 + cc]);
        }
        #pragma unroll
        for (int i = 0; i < 2; i++) {
            int idx = i * 256 + t;
            if (MODE == 0) {
                int row = idx >> 4, cc = (idx & 15) * 4;
                cp16(&Bbase[row * 72 + cc], &PB[(size_t)(kb + row) * CDIM + c0 + cc]);
            } else {
                int row = idx >> 3, cc = (idx & 7) * 4;
                cp16(&Bbase[row * 36 + cc], &PB[(size_t)(c0 + row) * CDIM + kb + cc]);
            }
        }
    };

    float acc[2][2][4] = {};

    issue(0, 0);  CP_COMMIT();
    issue(1, 32); CP_COMMIT();

    for (int c = 0; c < 8; c++) {
        CP_WAIT1();
        __syncthreads();
        if (c + 2 < 8) issue((c + 2) % 3, (c + 2) * 32);
        CP_COMMIT();

        float* A_ = smem + (c % 3) * STG;
        float* B_ = A_ + 32 * 72;
        #pragma unroll
        for (int kk = 0; kk < 32; kk += 8) {
            uint32_t a[2][4], bb[2][2];
            #pragma unroll
            for (int ms = 0; ms < 2; ms++) {
                int bm = wm * 32 + ms * 16;
                a[ms][0] = f2tf(A_[(kk + tq) * 72 + bm + g]);
                a[ms][1] = f2tf(A_[(kk + tq) * 72 + bm + g + 8]);
                a[ms][2] = f2tf(A_[(kk + 4 + tq) * 72 + bm + g]);
                a[ms][3] = f2tf(A_[(kk + 4 + tq) * 72 + bm + g + 8]);
            }
            #pragma unroll
            for (int cs = 0; cs < 2; cs++) {
                int bc = wc * 16 + cs * 8;
                if (MODE == 0) {
                    bb[cs][0] = f2tf(B_[(kk + tq) * 72 + bc + g]);
                    bb[cs][1] = f2tf(B_[(kk + 4 + tq) * 72 + bc + g]);
                } else {
                    bb[cs][0] = f2tf(B_[(bc + g) * 36 + kk + tq]);
                    bb[cs][1] = f2tf(B_[(bc + g) * 36 + kk + 4 + tq]);
                }
            }
            #pragma unroll
            for (int ms = 0; ms < 2; ms++)
                #pragma unroll
                for (int cs = 0; cs < 2; cs++)
                    mma_tf32(acc[ms][cs], a[ms], bb[cs]);
        }
    }

    #pragma unroll
    for (int ms = 0; ms < 2; ms++) {
        int mb = m0 + wm * 32 + ms * 16;
        int r0 = mb + g, r1 = mb + g + 8;
        #pragma unroll
        for (int cs = 0; cs < 2; cs++) {
            int c = c0 + wc * 16 + cs * 8 + tq * 2;
            if (MODE == 0) {
                float2 b2 = *(const float2*)&bias[c];
                float2 v0 = {acc[ms][cs][0] + b2.x, acc[ms][cs][1] + b2.y};
                float2 v1 = {acc[ms][cs][2] + b2.x, acc[ms][cs][3] + b2.y};
                *(float2*)&outp[(size_t)r0 * OS + c] = v0;
                *(float2*)&outp[(size_t)r1 * OS + c] = v1;
            } else {
                float br0 = bias[r0], br1 = bias[r1];
                float2 v0 = {acc[ms][cs][0] + br0, acc[ms][cs][1] + br0};
                float2 v1 = {acc[ms][cs][2] + br1, acc[ms][cs][3] + br1};
                *(float2*)&outp[(size_t)r0 * OS + c] = v0;
                *(float2*)&outp[(size_t)r1 * OS + c] = v1;
            }
        }
    }
}

// ---------------- fused block sparse attention (bank-conflict-free) ----------------
__global__ __launch_bounds__(256) void attn_kernel(const float* __restrict__ qproj,
                                                   const float* __restrict__ kproj,
                                                   const float* __restrict__ vproj,
                                                   const int* __restrict__ idx,
                                                   float* __restrict__ x) {
    int qlow = blockIdx.x;
    int b    = blockIdx.y;
    extern __shared__ float sm[];
    float4* Ks4 = (float4*)sm;                       // [32][64] float4, swizzled
    float4* Vs4 = (float4*)(sm + KLEN * CDIM);
    __shared__ int sidx[KLEN];
    int t = threadIdx.x;
    if (t < KLEN) sidx[t] = idx[((size_t)b * NLOW + qlow) * KLEN + t];
    __syncthreads();

    const float4* kp4 = (const float4*)kproj;
    const float4* vp4 = (const float4*)vproj;
    #pragma unroll
    for (int c = 0; c < 8; c++) {
        int li = c * 256 + t;              // 0..2047
        int r  = li >> 6;
        int c4 = li & 63;
        int dc = c4 ^ ((c4 >> 3) & 7);     // swizzled column
        size_t src = ((size_t)(b * NPIX + sidx[r])) * 64 + c4;
        Ks4[r * 64 + dc] = kp4[src];
        Vs4[r * 64 + dc] = vp4[src];
    }
    __syncthreads();

    int kk = t & 1;
    int h  = (t >> 1) & 7;
    int q  = t >> 4;
    int n  = qlow * 16 + q;

    float qreg[HD];
    const float4* qp4 = (const float4*)(qproj + ((size_t)(b * NPIX + n)) * CDIM + h * HD);
    #pragma unroll
    for (int d4 = 0; d4 < 8; d4++) {
        float4 v = qp4[d4];
        qreg[d4 * 4 + 0] = v.x; qreg[d4 * 4 + 1] = v.y;
        qreg[d4 * 4 + 2] = v.z; qreg[d4 * 4 + 3] = v.w;
    }

    const float scale = 0.17677669529663687f;  // 32^-0.5
    float s[16];
    #pragma unroll
    for (int j = 0; j < 16; j++) {
        int k = kk * 16 + j;
        const float4* kr = Ks4 + k * 64 + h * 8;
        float acc = 0.f;
        #pragma unroll
        for (int d4 = 0; d4 < 8; d4++) {
            float4 kv = kr[d4 ^ h];
            acc += qreg[d4 * 4 + 0] * kv.x + qreg[d4 * 4 + 1] * kv.y
                 + qreg[d4 * 4 + 2] * kv.z + qreg[d4 * 4 + 3] * kv.w;
        }
        s[j] = acc * scale;
    }

    float mloc = s[0];
    #pragma unroll
    for (int j = 1; j < 16; j++) mloc = fmaxf(mloc, s[j]);
    float m = fmaxf(mloc, __shfl_xor_sync(0xffffffffu, mloc, 1));

    float ssum = 0.f;
    #pragma unroll
    for (int j = 0; j < 16; j++) { s[j] = __expf(s[j] - m); ssum += s[j]; }

    float o[HD] = {};
    #pragma unroll
    for (int j = 0; j < 16; j++) {
        int k = kk * 16 + j;
        float p = s[j];
        const float4* vr = Vs4 + k * 64 + h * 8;
        #pragma unroll
        for (int d4 = 0; d4 < 8; d4++) {
            float4 vv = vr[d4 ^ h];
            o[d4 * 4 + 0] += p * vv.x; o[d4 * 4 + 1] += p * vv.y;
            o[d4 * 4 + 2] += p * vv.z; o[d4 * 4 + 3] += p * vv.w;
        }
    }

    float stot = ssum + __shfl_xor_sync(0xffffffffu, ssum, 1);
    float inv = 1.f / stot;

    float od[16];
    #pragma unroll
    for (int j = 0; j < 16; j++) {
        float t0 = o[j]      + __shfl_xor_sync(0xffffffffu, o[j],      1);
        float t1 = o[j + 16] + __shfl_xor_sync(0xffffffffu, o[j + 16], 1);
        od[j] = (kk ? t1 : t0) * inv;
    }
    float4* xo = (float4*)(x + ((size_t)(b * NPIX + n)) * CDIM + h * HD + kk * 16);
    #pragma unroll
    for (int d4 = 0; d4 < 4; d4++) {
        float4 r = {od[d4 * 4 + 0], od[d4 * 4 + 1], od[d4 * 4 + 2], od[d4 * 4 + 3]};
        xo[d4] = r;
    }
}

// ---------------- launch ----------------
extern "C" void kernel_launch(void* const* d_in, const int* in_sizes, int n_in,
                              void* d_out, int out_size) {
    const float* qh   = (const float*)d_in[0];
    const float* kh   = (const float*)d_in[1];
    const float* vh   = (const float*)d_in[2];
    const float* cmap = (const float*)d_in[3];
    const float* Wq   = (const float*)d_in[4];
    const float* bq   = (const float*)d_in[5];
    const float* Wk   = (const float*)d_in[6];
    const float* bk   = (const float*)d_in[7];
    const float* Wv   = (const float*)d_in[8];
    const float* bv   = (const float*)d_in[9];
    const float* Wo   = (const float*)d_in[10];
    const float* bo   = (const float*)d_in[11];
    float* out = (float*)d_out;

    float *pq, *pk, *pv, *px;
    int* pidx;
    cudaGetSymbolAddress((void**)&pq,   g_q);
    cudaGetSymbolAddress((void**)&pk,   g_k);
    cudaGetSymbolAddress((void**)&pv,   g_v);
    cudaGetSymbolAddress((void**)&px,   g_x);
    cudaGetSymbolAddress((void**)&pidx, g_idx);

    const int GS = STG * 3 * sizeof(float);   // 55296 B
    cudaFuncSetAttribute(gemm_tf32<0>, cudaFuncAttributeMaxDynamicSharedMemorySize, GS);
    cudaFuncSetAttribute(gemm_tf32<1>, cudaFuncAttributeMaxDynamicSharedMemorySize, GS);
    cudaFuncSetAttribute(attn_kernel, cudaFuncAttributeMaxDynamicSharedMemorySize, 65536);

    topk_expand_kernel<<<64, 256>>>(cmap, pidx);

    dim3 gp(NPIX / 64, CDIM / 64, 6);
    gemm_tf32<0><<<gp, 256, GS>>>(qh, kh, vh, Wq, Wk, Wv, bq, bk, bv, pq, pk, pv);

    attn_kernel<<<dim3(NLOW, BATCH), 256, 65536>>>(pq, pk, pv, pidx, px);

    dim3 go(CDIM / 64, NPIX / 64, BATCH);
    gemm_tf32<1><<<go, 256, GS>>>(px, nullptr, nullptr, Wo, nullptr, nullptr,
                                  bo, nullptr, nullptr, out, nullptr, nullptr);
}

// round 7
// speedup vs baseline: 2.6569x; 1.0404x over previous
#include <cuda_runtime.h>
#include <math.h>
#include <stdint.h>

#define NPIX 4096
#define CDIM 256
#define NLOW 256
#define KLEN 32
#define NHEADS 8
#define HD 32
#define BATCH 2

// ---------------- scratch (no allocations allowed) ----------------
__device__ float    g_q[BATCH * NPIX * CDIM];   // fp32 (B,N,C)
__device__ float    g_k[BATCH * NPIX * CDIM];
__device__ float    g_v[BATCH * NPIX * CDIM];
__device__ float    g_x[BATCH * NPIX * CDIM];   // tf32 bits
__device__ uint32_t g_w[4 * CDIM * CDIM];       // Wq,Wk,Wv,Wo as tf32 bits
__device__ int      g_idx[BATCH * NLOW * KLEN];

// ---------------- helpers ----------------
__device__ __forceinline__ uint32_t f2tf(float x) {
    uint32_t r;
    asm("cvt.rna.tf32.f32 %0, %1;" : "=r"(r) : "f"(x));
    return r;
}
__device__ __forceinline__ void mma_tf32(float* c, const uint32_t* a, const uint32_t* b) {
    asm volatile(
        "mma.sync.aligned.m16n8k8.row.col.f32.tf32.tf32.f32 "
        "{%0,%1,%2,%3},{%4,%5,%6,%7},{%8,%9},{%0,%1,%2,%3};"
        : "+f"(c[0]), "+f"(c[1]), "+f"(c[2]), "+f"(c[3])
        : "r"(a[0]), "r"(a[1]), "r"(a[2]), "r"(a[3]), "r"(b[0]), "r"(b[1]));
}
__device__ __forceinline__ void cp16(const void* dst, const void* src) {
    uint32_t d = (uint32_t)__cvta_generic_to_shared(dst);
    asm volatile("cp.async.cg.shared.global [%0], [%1], 16;" :: "r"(d), "l"(src));
}
#define CP_COMMIT() asm volatile("cp.async.commit_group;" ::: "memory")
#define CP_WAIT0()  asm volatile("cp.async.wait_group 0;" ::: "memory")

// ---------------- weight pre-convert: fp32 -> tf32 bits ----------------
__global__ __launch_bounds__(256) void wconv_kernel(const float* __restrict__ Wq,
                                                    const float* __restrict__ Wk,
                                                    const float* __restrict__ Wv,
                                                    const float* __restrict__ Wo,
                                                    uint32_t* __restrict__ gw) {
    int i = blockIdx.x * 256 + threadIdx.x;       // 0..65535 float4 units
    int which = i >> 14;                          // 16384 float4 per matrix
    int off = (i & 16383) * 4;
    const float* src = (which == 0) ? Wq : (which == 1) ? Wk : (which == 2) ? Wv : Wo;
    float4 v = *(const float4*)&src[off];
    uint4 r = {f2tf(v.x), f2tf(v.y), f2tf(v.z), f2tf(v.w)};
    *(uint4*)&gw[which * 65536 + off] = r;
}

// ---------------- top-2 + index expansion (one warp per row) ----------------
__global__ __launch_bounds__(256) void topk_expand_kernel(const float* __restrict__ cmap,
                                                          int* __restrict__ idx) {
    int lane = threadIdx.x & 31;
    int row  = blockIdx.x * 8 + (threadIdx.x >> 5);
    const float* r = cmap + (size_t)row * NLOW;
    float m1 = -1e30f, m2 = -1e30f;
    int i1 = 0, i2 = 0;
    #pragma unroll
    for (int l = 0; l < 8; l++) {
        int j = l * 32 + lane;
        float v = r[j];
        if (v > m1)      { m2 = m1; i2 = i1; m1 = v; i1 = j; }
        else if (v > m2) { m2 = v;  i2 = j; }
    }
    #pragma unroll
    for (int off = 16; off > 0; off >>= 1) {
        float om1 = __shfl_xor_sync(0xffffffffu, m1, off);
        float om2 = __shfl_xor_sync(0xffffffffu, m2, off);
        int   oi1 = __shfl_xor_sync(0xffffffffu, i1, off);
        int   oi2 = __shfl_xor_sync(0xffffffffu, i2, off);
        if (om1 > m1) {
            if (m1 > om2) { m2 = m1; i2 = i1; } else { m2 = om2; i2 = oi2; }
            m1 = om1; i1 = oi1;
        } else if (om1 > m2) { m2 = om1; i2 = oi1; }
    }
    int t   = (lane < 16) ? i1 : i2;
    int pos = lane & 15;
    int r0  = (t >> 4) << 2;
    int c0  = (t & 15) << 2;
    idx[(size_t)row * KLEN + lane] = (r0 + (pos >> 2)) * 64 + c0 + (pos & 3);
}

// ---------------- tf32 GEMM: 128x64 CTA tile, CVT-free mainloop ----------------
// MODE 0 (fused QKV proj): grid (32, 4, 6=which*2+b).
//   A (C,NPIX) fp32, m-contig; staged LDG->cvt->STS. B = g_w tf32 via cp.async. out (NPIX,C) fp32.
// MODE 1 (out proj): grid (2, 64, 2=b).
//   A = Wo tf32 (k-major, cout contig) cp.async; B = x tf32 (k contig) cp.async n-major.
//   out (C,NPIX), float2 pixel-contiguous stores.
// 8 warps = 4(m) x 2(n); warp tile 32x32; K-chunk 32; double-buffered.
#define AW 136
#define A_WORDS (32 * AW)     // 4352
#define B_WORDS 2304          // 32*72 (MODE0) or 64*36 (MODE1)
#define STW (A_WORDS + B_WORDS)
#define GSMEM (2 * STW * 4)   // 53248 B

template<int MODE>
__global__ __launch_bounds__(256) void gemm_tf32(
    const float* __restrict__ Aq, const float* __restrict__ Ak, const float* __restrict__ Av,
    const uint32_t* __restrict__ gw,
    const float* __restrict__ bq, const float* __restrict__ bk, const float* __restrict__ bv,
    float* __restrict__ oq, float* __restrict__ ok2, float* __restrict__ ov) {
    extern __shared__ uint32_t sw[];
    int m0 = blockIdx.x * 128;
    int c0 = blockIdx.y * 64;
    int t    = threadIdx.x;
    int lane = t & 31, w = t >> 5;
    int wm = w & 3, wc = w >> 2;
    int g = lane >> 2, tq = lane & 3;

    const float* PA;          // MODE0: fp32 feats; MODE1: Wo tf32 bits (as float*)
    const uint32_t* PB;       // tf32 bits
    const float* bias;
    float* outp;  size_t OS;

    if (MODE == 0) {
        int which = blockIdx.z >> 1, b = blockIdx.z & 1;
        const float* Ain = (which == 0) ? Aq : (which == 1) ? Ak : Av;
        PA   = Ain + (size_t)b * CDIM * NPIX;
        PB   = gw + (size_t)which * 65536;
        bias = (which == 0) ? bq : (which == 1) ? bk : bv;
        float* Out = (which == 0) ? oq : (which == 1) ? ok2 : ov;
        outp = Out + (size_t)b * NPIX * CDIM;  OS = CDIM;
    } else {
        int b = blockIdx.z;
        PA   = (const float*)(gw + 3 * 65536);          // Wo tf32, m=cout contig
        PB   = (const uint32_t*)(Aq + (size_t)b * NPIX * CDIM);  // x tf32, k contig
        bias = bq;
        outp = oq + (size_t)b * CDIM * NPIX;  OS = NPIX;
    }

    float acc[2][2][4] = {};   // [ms][cs pair of 2? no: see below]
    float accx[2][4][4];       // real acc: [ms][cs][4]
    (void)acc;
    #pragma unroll
    for (int ms = 0; ms < 2; ms++)
        #pragma unroll
        for (int cs = 0; cs < 4; cs++)
            #pragma unroll
            for (int r = 0; r < 4; r++) accx[ms][cs][r] = 0.f;

    float4 pa[4];

    auto ldgA = [&](int kb) {        // MODE0 only: raw fp32 A
        #pragma unroll
        for (int p = 0; p < 4; p++) {
            int idx = p * 256 + t;
            int k = idx >> 5, m4 = idx & 31;
            pa[p] = *(const float4*)&PA[(size_t)(kb + k) * NPIX + m0 + m4 * 4];
        }
    };
    auto stsA = [&](int s) {         // MODE0 only: cvt + vector STS
        uint32_t* A_ = sw + s * STW;
        #pragma unroll
        for (int p = 0; p < 4; p++) {
            int idx = p * 256 + t;
            int k = idx >> 5, m4 = idx & 31;
            uint4 v = {f2tf(pa[p].x), f2tf(pa[p].y), f2tf(pa[p].z), f2tf(pa[p].w)};
            *(uint4*)&A_[k * AW + m4 * 4] = v;
        }
    };
    auto cpStage = [&](int s, int kb) {
        uint32_t* A_ = sw + s * STW;
        uint32_t* B_ = A_ + A_WORDS;
        if (MODE == 1) {
            #pragma unroll
            for (int p = 0; p < 4; p++) {
                int idx = p * 256 + t;
                int k = idx >> 5, m4 = idx & 31;
                cp16(&A_[k * AW + m4 * 4], &PA[(size_t)(kb + k) * CDIM + m0 + m4 * 4]);
            }
            #pragma unroll
            for (int p = 0; p < 2; p++) {
                int idx = p * 256 + t;
                int n = idx >> 3, k4 = idx & 7;
                cp16(&B_[n * 36 + k4 * 4], &PB[(size_t)(c0 + n) * CDIM + kb + k4 * 4]);
            }
        } else {
            #pragma unroll
            for (int p = 0; p < 2; p++) {
                int idx = p * 256 + t;
                int k = idx >> 4, n4 = idx & 15;
                cp16(&B_[k * 72 + n4 * 4], &PB[(size_t)(kb + k) * CDIM + c0 + n4 * 4]);
            }
        }
    };

    if (MODE == 0) ldgA(0);
    cpStage(0, 0); CP_COMMIT();
    if (MODE == 0) stsA(0);

    int s = 0;
    for (int c = 0; c < 8; c++, s ^= 1) {
        CP_WAIT0();
        __syncthreads();
        bool more = (c < 7);
        if (more) {
            if (MODE == 0) ldgA((c + 1) * 32);
            cpStage(s ^ 1, (c + 1) * 32);
            CP_COMMIT();
        }

        uint32_t* A_ = sw + s * STW;
        uint32_t* B_ = A_ + A_WORDS;
        #pragma unroll
        for (int kk = 0; kk < 32; kk += 8) {
            uint32_t a[2][4], bb[4][2];
            #pragma unroll
            for (int ms = 0; ms < 2; ms++) {
                int bm = wm * 32 + ms * 16;
                a[ms][0] = A_[(kk + tq) * AW + bm + g];
                a[ms][1] = A_[(kk + tq) * AW + bm + g + 8];
                a[ms][2] = A_[(kk + 4 + tq) * AW + bm + g];
                a[ms][3] = A_[(kk + 4 + tq) * AW + bm + g + 8];
            }
            #pragma unroll
            for (int cs = 0; cs < 4; cs++) {
                int bc = wc * 32 + cs * 8;
                if (MODE == 0) {
                    bb[cs][0] = B_[(kk + tq) * 72 + bc + g];
                    bb[cs][1] = B_[(kk + 4 + tq) * 72 + bc + g];
                } else {
                    bb[cs][0] = B_[(bc + g) * 36 + kk + tq];
                    bb[cs][1] = B_[(bc + g) * 36 + kk + 4 + tq];
                }
            }
            #pragma unroll
            for (int ms = 0; ms < 2; ms++)
                #pragma unroll
                for (int cs = 0; cs < 4; cs++)
                    mma_tf32(accx[ms][cs], a[ms], bb[cs]);
        }
        if (more && MODE == 0) stsA(s ^ 1);
    }

    #pragma unroll
    for (int ms = 0; ms < 2; ms++) {
        int mb = m0 + wm * 32 + ms * 16;
        int r0 = mb + g, r1 = mb + g + 8;
        #pragma unroll
        for (int cs = 0; cs < 4; cs++) {
            int c = c0 + wc * 32 + cs * 8 + tq * 2;
            if (MODE == 0) {
                float2 b2 = *(const float2*)&bias[c];
                float2 v0 = {accx[ms][cs][0] + b2.x, accx[ms][cs][1] + b2.y};
                float2 v1 = {accx[ms][cs][2] + b2.x, accx[ms][cs][3] + b2.y};
                *(float2*)&outp[(size_t)r0 * OS + c] = v0;
                *(float2*)&outp[(size_t)r1 * OS + c] = v1;
            } else {
                float br0 = bias[r0], br1 = bias[r1];
                float2 v0 = {accx[ms][cs][0] + br0, accx[ms][cs][1] + br0};
                float2 v1 = {accx[ms][cs][2] + br1, accx[ms][cs][3] + br1};
                *(float2*)&outp[(size_t)r0 * OS + c] = v0;
                *(float2*)&outp[(size_t)r1 * OS + c] = v1;
            }
        }
    }
}

// ---------------- fused block sparse attention (bank-conflict-free) ----------------
__global__ __launch_bounds__(256) void attn_kernel(const float* __restrict__ qproj,
                                                   const float* __restrict__ kproj,
                                                   const float* __restrict__ vproj,
                                                   const int* __restrict__ idx,
                                                   float* __restrict__ x) {
    int qlow = blockIdx.x;
    int b    = blockIdx.y;
    extern __shared__ float sm[];
    float4* Ks4 = (float4*)sm;
    float4* Vs4 = (float4*)(sm + KLEN * CDIM);
    __shared__ int sidx[KLEN];
    int t = threadIdx.x;
    if (t < KLEN) sidx[t] = idx[((size_t)b * NLOW + qlow) * KLEN + t];
    __syncthreads();

    const float4* kp4 = (const float4*)kproj;
    const float4* vp4 = (const float4*)vproj;
    #pragma unroll
    for (int c = 0; c < 8; c++) {
        int li = c * 256 + t;
        int r  = li >> 6;
        int c4 = li & 63;
        int dc = c4 ^ ((c4 >> 3) & 7);
        size_t src = ((size_t)(b * NPIX + sidx[r])) * 64 + c4;
        Ks4[r * 64 + dc] = kp4[src];
        Vs4[r * 64 + dc] = vp4[src];
    }
    __syncthreads();

    int kk = t & 1;
    int h  = (t >> 1) & 7;
    int q  = t >> 4;
    int n  = qlow * 16 + q;

    float qreg[HD];
    const float4* qp4 = (const float4*)(qproj + ((size_t)(b * NPIX + n)) * CDIM + h * HD);
    #pragma unroll
    for (int d4 = 0; d4 < 8; d4++) {
        float4 v = qp4[d4];
        qreg[d4 * 4 + 0] = v.x; qreg[d4 * 4 + 1] = v.y;
        qreg[d4 * 4 + 2] = v.z; qreg[d4 * 4 + 3] = v.w;
    }

    const float scale = 0.17677669529663687f;
    float s[16];
    #pragma unroll
    for (int j = 0; j < 16; j++) {
        int k = kk * 16 + j;
        const float4* kr = Ks4 + k * 64 + h * 8;
        float acc = 0.f;
        #pragma unroll
        for (int d4 = 0; d4 < 8; d4++) {
            float4 kv = kr[d4 ^ h];
            acc += qreg[d4 * 4 + 0] * kv.x + qreg[d4 * 4 + 1] * kv.y
                 + qreg[d4 * 4 + 2] * kv.z + qreg[d4 * 4 + 3] * kv.w;
        }
        s[j] = acc * scale;
    }

    float mloc = s[0];
    #pragma unroll
    for (int j = 1; j < 16; j++) mloc = fmaxf(mloc, s[j]);
    float m = fmaxf(mloc, __shfl_xor_sync(0xffffffffu, mloc, 1));

    float ssum = 0.f;
    #pragma unroll
    for (int j = 0; j < 16; j++) { s[j] = __expf(s[j] - m); ssum += s[j]; }

    float o[HD] = {};
    #pragma unroll
    for (int j = 0; j < 16; j++) {
        int k = kk * 16 + j;
        float p = s[j];
        const float4* vr = Vs4 + k * 64 + h * 8;
        #pragma unroll
        for (int d4 = 0; d4 < 8; d4++) {
            float4 vv = vr[d4 ^ h];
            o[d4 * 4 + 0] += p * vv.x; o[d4 * 4 + 1] += p * vv.y;
            o[d4 * 4 + 2] += p * vv.z; o[d4 * 4 + 3] += p * vv.w;
        }
    }

    float stot = ssum + __shfl_xor_sync(0xffffffffu, ssum, 1);
    float inv = 1.f / stot;

    float od[16];
    #pragma unroll
    for (int j = 0; j < 16; j++) {
        float t0 = o[j]      + __shfl_xor_sync(0xffffffffu, o[j],      1);
        float t1 = o[j + 16] + __shfl_xor_sync(0xffffffffu, o[j + 16], 1);
        od[j] = (kk ? t1 : t0) * inv;
    }
    // store tf32 bits: consumed raw by the output GEMM (cvt-free mainloop)
    float4* xo = (float4*)(x + ((size_t)(b * NPIX + n)) * CDIM + h * HD + kk * 16);
    #pragma unroll
    for (int d4 = 0; d4 < 4; d4++) {
        float4 r = {__uint_as_float(f2tf(od[d4 * 4 + 0])), __uint_as_float(f2tf(od[d4 * 4 + 1])),
                    __uint_as_float(f2tf(od[d4 * 4 + 2])), __uint_as_float(f2tf(od[d4 * 4 + 3]))};
        xo[d4] = r;
    }
}

// ---------------- launch ----------------
extern "C" void kernel_launch(void* const* d_in, const int* in_sizes, int n_in,
                              void* d_out, int out_size) {
    const float* qh   = (const float*)d_in[0];
    const float* kh   = (const float*)d_in[1];
    const float* vh   = (const float*)d_in[2];
    const float* cmap = (const float*)d_in[3];
    const float* Wq   = (const float*)d_in[4];
    const float* bq   = (const float*)d_in[5];
    const float* Wk   = (const float*)d_in[6];
    const float* bk   = (const float*)d_in[7];
    const float* Wv   = (const float*)d_in[8];
    const float* bv   = (const float*)d_in[9];
    const float* Wo   = (const float*)d_in[10];
    const float* bo   = (const float*)d_in[11];
    float* out = (float*)d_out;

    float *pq, *pk, *pv, *px;
    uint32_t* pw;
    int* pidx;
    cudaGetSymbolAddress((void**)&pq,   g_q);
    cudaGetSymbolAddress((void**)&pk,   g_k);
    cudaGetSymbolAddress((void**)&pv,   g_v);
    cudaGetSymbolAddress((void**)&px,   g_x);
    cudaGetSymbolAddress((void**)&pw,   g_w);
    cudaGetSymbolAddress((void**)&pidx, g_idx);

    cudaFuncSetAttribute(gemm_tf32<0>, cudaFuncAttributeMaxDynamicSharedMemorySize, GSMEM);
    cudaFuncSetAttribute(gemm_tf32<1>, cudaFuncAttributeMaxDynamicSharedMemorySize, GSMEM);
    cudaFuncSetAttribute(attn_kernel, cudaFuncAttributeMaxDynamicSharedMemorySize, 65536);

    topk_expand_kernel<<<64, 256>>>(cmap, pidx);
    wconv_kernel<<<256, 256>>>(Wq, Wk, Wv, Wo, pw);

    dim3 gp(NPIX / 128, CDIM / 64, 6);
    gemm_tf32<0><<<gp, 256, GSMEM>>>(qh, kh, vh, pw, bq, bk, bv, pq, pk, pv);

    attn_kernel<<<dim3(NLOW, BATCH), 256, 65536>>>(pq, pk, pv, pidx, px);

    dim3 go(CDIM / 128, NPIX / 64, BATCH);
    gemm_tf32<1><<<go, 256, GSMEM>>>(px, nullptr, nullptr, pw,
                                     bo, nullptr, nullptr, out, nullptr, nullptr);
}

// round 8
// speedup vs baseline: 2.7362x; 1.0299x over previous
#include <cuda_runtime.h>
#include <math.h>
#include <stdint.h>

#define NPIX 4096
#define CDIM 256
#define NLOW 256
#define KLEN 32
#define NHEADS 8
#define HD 32
#define BATCH 2

// ---------------- scratch (no allocations allowed) ----------------
__device__ float    g_q[BATCH * NPIX * CDIM];   // fp32 (B,N,C)
__device__ float    g_k[BATCH * NPIX * CDIM];
__device__ float    g_v[BATCH * NPIX * CDIM];
__device__ float    g_x[BATCH * NPIX * CDIM];   // tf32 bits
__device__ uint32_t g_w[4 * CDIM * CDIM];       // Wq,Wk,Wv,Wo as tf32 bits
__device__ int      g_idx[BATCH * NLOW * KLEN];

// ---------------- helpers ----------------
__device__ __forceinline__ uint32_t f2tf(float x) {
    uint32_t r;
    asm("cvt.rna.tf32.f32 %0, %1;" : "=r"(r) : "f"(x));
    return r;
}
__device__ __forceinline__ void mma_tf32(float* c, const uint32_t* a, const uint32_t* b) {
    asm volatile(
        "mma.sync.aligned.m16n8k8.row.col.f32.tf32.tf32.f32 "
        "{%0,%1,%2,%3},{%4,%5,%6,%7},{%8,%9},{%0,%1,%2,%3};"
        : "+f"(c[0]), "+f"(c[1]), "+f"(c[2]), "+f"(c[3])
        : "r"(a[0]), "r"(a[1]), "r"(a[2]), "r"(a[3]), "r"(b[0]), "r"(b[1]));
}
__device__ __forceinline__ void cp16(const void* dst, const void* src) {
    uint32_t d = (uint32_t)__cvta_generic_to_shared(dst);
    asm volatile("cp.async.cg.shared.global [%0], [%1], 16;" :: "r"(d), "l"(src));
}
#define CP_COMMIT() asm volatile("cp.async.commit_group;" ::: "memory")
#define CP_WAIT0()  asm volatile("cp.async.wait_group 0;" ::: "memory")
#define CP_WAIT1()  asm volatile("cp.async.wait_group 1;" ::: "memory")

// ---------------- weight pre-convert: fp32 -> tf32 bits ----------------
__global__ __launch_bounds__(256) void wconv_kernel(const float* __restrict__ Wq,
                                                    const float* __restrict__ Wk,
                                                    const float* __restrict__ Wv,
                                                    const float* __restrict__ Wo,
                                                    uint32_t* __restrict__ gw) {
    int i = blockIdx.x * 256 + threadIdx.x;
    int which = i >> 14;
    int off = (i & 16383) * 4;
    const float* src = (which == 0) ? Wq : (which == 1) ? Wk : (which == 2) ? Wv : Wo;
    float4 v = *(const float4*)&src[off];
    uint4 r = {f2tf(v.x), f2tf(v.y), f2tf(v.z), f2tf(v.w)};
    *(uint4*)&gw[which * 65536 + off] = r;
}

// ---------------- top-2 + index expansion (one warp per row) ----------------
__global__ __launch_bounds__(256) void topk_expand_kernel(const float* __restrict__ cmap,
                                                          int* __restrict__ idx) {
    int lane = threadIdx.x & 31;
    int row  = blockIdx.x * 8 + (threadIdx.x >> 5);
    const float* r = cmap + (size_t)row * NLOW;
    float m1 = -1e30f, m2 = -1e30f;
    int i1 = 0, i2 = 0;
    #pragma unroll
    for (int l = 0; l < 8; l++) {
        int j = l * 32 + lane;
        float v = r[j];
        if (v > m1)      { m2 = m1; i2 = i1; m1 = v; i1 = j; }
        else if (v > m2) { m2 = v;  i2 = j; }
    }
    #pragma unroll
    for (int off = 16; off > 0; off >>= 1) {
        float om1 = __shfl_xor_sync(0xffffffffu, m1, off);
        float om2 = __shfl_xor_sync(0xffffffffu, m2, off);
        int   oi1 = __shfl_xor_sync(0xffffffffu, i1, off);
        int   oi2 = __shfl_xor_sync(0xffffffffu, i2, off);
        if (om1 > m1) {
            if (m1 > om2) { m2 = m1; i2 = i1; } else { m2 = om2; i2 = oi2; }
            m1 = om1; i1 = oi1;
        } else if (om1 > m2) { m2 = om1; i2 = oi1; }
    }
    int t   = (lane < 16) ? i1 : i2;
    int pos = lane & 15;
    int r0  = (t >> 4) << 2;
    int c0  = (t & 15) << 2;
    idx[(size_t)row * KLEN + lane] = (r0 + (pos >> 2)) * 64 + c0 + (pos & 3);
}

// ---------------- tf32 GEMM: 128x64 CTA tile, CVT-free mainloop ----------------
#define AW 136
#define A_WORDS (32 * AW)
#define B_WORDS 2304
#define STW (A_WORDS + B_WORDS)
#define GSMEM (2 * STW * 4)

template<int MODE>
__global__ __launch_bounds__(256) void gemm_tf32(
    const float* __restrict__ Aq, const float* __restrict__ Ak, const float* __restrict__ Av,
    const uint32_t* __restrict__ gw,
    const float* __restrict__ bq, const float* __restrict__ bk, const float* __restrict__ bv,
    float* __restrict__ oq, float* __restrict__ ok2, float* __restrict__ ov) {
    extern __shared__ uint32_t sw[];
    int m0 = blockIdx.x * 128;
    int c0 = blockIdx.y * 64;
    int t    = threadIdx.x;
    int lane = t & 31, w = t >> 5;
    int wm = w & 3, wc = w >> 2;
    int g = lane >> 2, tq = lane & 3;

    const float* PA;
    const uint32_t* PB;
    const float* bias;
    float* outp;  size_t OS;

    if (MODE == 0) {
        int which = blockIdx.z >> 1, b = blockIdx.z & 1;
        const float* Ain = (which == 0) ? Aq : (which == 1) ? Ak : Av;
        PA   = Ain + (size_t)b * CDIM * NPIX;
        PB   = gw + (size_t)which * 65536;
        bias = (which == 0) ? bq : (which == 1) ? bk : bv;
        float* Out = (which == 0) ? oq : (which == 1) ? ok2 : ov;
        outp = Out + (size_t)b * NPIX * CDIM;  OS = CDIM;
    } else {
        int b = blockIdx.z;
        PA   = (const float*)(gw + 3 * 65536);
        PB   = (const uint32_t*)(Aq + (size_t)b * NPIX * CDIM);
        bias = bq;
        outp = oq + (size_t)b * CDIM * NPIX;  OS = NPIX;
    }

    float accx[2][4][4];
    #pragma unroll
    for (int ms = 0; ms < 2; ms++)
        #pragma unroll
        for (int cs = 0; cs < 4; cs++)
            #pragma unroll
            for (int r = 0; r < 4; r++) accx[ms][cs][r] = 0.f;

    float4 pa[4];

    auto ldgA = [&](int kb) {
        #pragma unroll
        for (int p = 0; p < 4; p++) {
            int idx = p * 256 + t;
            int k = idx >> 5, m4 = idx & 31;
            pa[p] = *(const float4*)&PA[(size_t)(kb + k) * NPIX + m0 + m4 * 4];
        }
    };
    auto stsA = [&](int s) {
        uint32_t* A_ = sw + s * STW;
        #pragma unroll
        for (int p = 0; p < 4; p++) {
            int idx = p * 256 + t;
            int k = idx >> 5, m4 = idx & 31;
            uint4 v = {f2tf(pa[p].x), f2tf(pa[p].y), f2tf(pa[p].z), f2tf(pa[p].w)};
            *(uint4*)&A_[k * AW + m4 * 4] = v;
        }
    };
    auto cpStage = [&](int s, int kb) {
        uint32_t* A_ = sw + s * STW;
        uint32_t* B_ = A_ + A_WORDS;
        if (MODE == 1) {
            #pragma unroll
            for (int p = 0; p < 4; p++) {
                int idx = p * 256 + t;
                int k = idx >> 5, m4 = idx & 31;
                cp16(&A_[k * AW + m4 * 4], &PA[(size_t)(kb + k) * CDIM + m0 + m4 * 4]);
            }
            #pragma unroll
            for (int p = 0; p < 2; p++) {
                int idx = p * 256 + t;
                int n = idx >> 3, k4 = idx & 7;
                cp16(&B_[n * 36 + k4 * 4], &PB[(size_t)(c0 + n) * CDIM + kb + k4 * 4]);
            }
        } else {
            #pragma unroll
            for (int p = 0; p < 2; p++) {
                int idx = p * 256 + t;
                int k = idx >> 4, n4 = idx & 15;
                cp16(&B_[k * 72 + n4 * 4], &PB[(size_t)(kb + k) * CDIM + c0 + n4 * 4]);
            }
        }
    };

    if (MODE == 0) ldgA(0);
    cpStage(0, 0); CP_COMMIT();
    if (MODE == 0) stsA(0);

    int s = 0;
    for (int c = 0; c < 8; c++, s ^= 1) {
        CP_WAIT0();
        __syncthreads();
        bool more = (c < 7);
        if (more) {
            if (MODE == 0) ldgA((c + 1) * 32);
            cpStage(s ^ 1, (c + 1) * 32);
            CP_COMMIT();
        }

        uint32_t* A_ = sw + s * STW;
        uint32_t* B_ = A_ + A_WORDS;
        #pragma unroll
        for (int kk = 0; kk < 32; kk += 8) {
            uint32_t a[2][4], bb[4][2];
            #pragma unroll
            for (int ms = 0; ms < 2; ms++) {
                int bm = wm * 32 + ms * 16;
                a[ms][0] = A_[(kk + tq) * AW + bm + g];
                a[ms][1] = A_[(kk + tq) * AW + bm + g + 8];
                a[ms][2] = A_[(kk + 4 + tq) * AW + bm + g];
                a[ms][3] = A_[(kk + 4 + tq) * AW + bm + g + 8];
            }
            #pragma unroll
            for (int cs = 0; cs < 4; cs++) {
                int bc = wc * 32 + cs * 8;
                if (MODE == 0) {
                    bb[cs][0] = B_[(kk + tq) * 72 + bc + g];
                    bb[cs][1] = B_[(kk + 4 + tq) * 72 + bc + g];
                } else {
                    bb[cs][0] = B_[(bc + g) * 36 + kk + tq];
                    bb[cs][1] = B_[(bc + g) * 36 + kk + 4 + tq];
                }
            }
            #pragma unroll
            for (int ms = 0; ms < 2; ms++)
                #pragma unroll
                for (int cs = 0; cs < 4; cs++)
                    mma_tf32(accx[ms][cs], a[ms], bb[cs]);
        }
        if (more && MODE == 0) stsA(s ^ 1);
    }

    #pragma unroll
    for (int ms = 0; ms < 2; ms++) {
        int mb = m0 + wm * 32 + ms * 16;
        int r0 = mb + g, r1 = mb + g + 8;
        #pragma unroll
        for (int cs = 0; cs < 4; cs++) {
            int c = c0 + wc * 32 + cs * 8 + tq * 2;
            if (MODE == 0) {
                float2 b2 = *(const float2*)&bias[c];
                float2 v0 = {accx[ms][cs][0] + b2.x, accx[ms][cs][1] + b2.y};
                float2 v1 = {accx[ms][cs][2] + b2.x, accx[ms][cs][3] + b2.y};
                *(float2*)&outp[(size_t)r0 * OS + c] = v0;
                *(float2*)&outp[(size_t)r1 * OS + c] = v1;
            } else {
                float br0 = bias[r0], br1 = bias[r1];
                float2 v0 = {accx[ms][cs][0] + br0, accx[ms][cs][1] + br0};
                float2 v1 = {accx[ms][cs][2] + br1, accx[ms][cs][3] + br1};
                *(float2*)&outp[(size_t)r0 * OS + c] = v0;
                *(float2*)&outp[(size_t)r1 * OS + c] = v1;
            }
        }
    }
}

// ---------------- fused block sparse attention, head-split + cp.async ----------------
// CTA = (qlow, b, head-half hh). 128 threads = 16q x 4h x 2kk.
// K/V tiles: 32 keys x 128 dims (this CTA's 4 heads) = 16 KB each, cp.async.cg gather,
// K group waited first so scores overlap the V loads.
// Swizzle: float4 col c stored at c ^ ((c>>3)&7); reads at h*8+(d4^h) are conflict-free
// across the 4 local heads (2-way max on the kk pair).
__global__ __launch_bounds__(128) void attn_kernel(const float* __restrict__ qproj,
                                                   const float* __restrict__ kproj,
                                                   const float* __restrict__ vproj,
                                                   const int* __restrict__ idx,
                                                   float* __restrict__ x) {
    int qlow = blockIdx.x;
    int b    = blockIdx.y;
    int hh   = blockIdx.z;                 // head half: dims [hh*128, hh*128+128)
    extern __shared__ float sm[];
    float4* Ks4 = (float4*)sm;             // [32][32] float4, swizzled
    float4* Vs4 = Ks4 + 32 * 32;
    __shared__ int sidx[KLEN];
    int t = threadIdx.x;
    if (t < KLEN) sidx[t] = idx[((size_t)b * NLOW + qlow) * KLEN + t];
    __syncthreads();

    const float* kbase = kproj + (size_t)b * NPIX * CDIM + hh * 128;
    const float* vbase = vproj + (size_t)b * NPIX * CDIM + hh * 128;

    // gather K (group A)
    #pragma unroll
    for (int p = 0; p < 8; p++) {
        int li = p * 128 + t;              // 0..1023
        int r  = li >> 5;                  // key row
        int c4 = li & 31;
        int dc = c4 ^ ((c4 >> 3) & 7);
        cp16(&Ks4[r * 32 + dc], &kbase[(size_t)sidx[r] * CDIM + c4 * 4]);
    }
    CP_COMMIT();
    // gather V (group B)
    #pragma unroll
    for (int p = 0; p < 8; p++) {
        int li = p * 128 + t;
        int r  = li >> 5;
        int c4 = li & 31;
        int dc = c4 ^ ((c4 >> 3) & 7);
        cp16(&Vs4[r * 32 + dc], &vbase[(size_t)sidx[r] * CDIM + c4 * 4]);
    }
    CP_COMMIT();

    int kk = t & 1;
    int h  = (t >> 1) & 3;                 // local head 0..3
    int q  = t >> 3;                       // query 0..15
    int n  = qlow * 16 + q;

    // load q while gathers are in flight
    float qreg[HD];
    const float4* qp4 = (const float4*)(qproj + ((size_t)(b * NPIX + n)) * CDIM + hh * 128 + h * HD);
    #pragma unroll
    for (int d4 = 0; d4 < 8; d4++) {
        float4 v = qp4[d4];
        qreg[d4 * 4 + 0] = v.x; qreg[d4 * 4 + 1] = v.y;
        qreg[d4 * 4 + 2] = v.z; qreg[d4 * 4 + 3] = v.w;
    }

    CP_WAIT1();          // K tile ready (V still loading)
    __syncthreads();

    const float scale = 0.17677669529663687f;  // 32^-0.5
    float s[16];
    #pragma unroll
    for (int j = 0; j < 16; j++) {
        int k = kk * 16 + j;
        const float4* kr = Ks4 + k * 32 + h * 8;
        float acc = 0.f;
        #pragma unroll
        for (int d4 = 0; d4 < 8; d4++) {
            float4 kv = kr[d4 ^ h];
            acc += qreg[d4 * 4 + 0] * kv.x + qreg[d4 * 4 + 1] * kv.y
                 + qreg[d4 * 4 + 2] * kv.z + qreg[d4 * 4 + 3] * kv.w;
        }
        s[j] = acc * scale;
    }

    float mloc = s[0];
    #pragma unroll
    for (int j = 1; j < 16; j++) mloc = fmaxf(mloc, s[j]);
    float m = fmaxf(mloc, __shfl_xor_sync(0xffffffffu, mloc, 1));

    float ssum = 0.f;
    #pragma unroll
    for (int j = 0; j < 16; j++) { s[j] = __expf(s[j] - m); ssum += s[j]; }

    CP_WAIT0();          // V tile ready
    __syncthreads();

    float o[HD] = {};
    #pragma unroll
    for (int j = 0; j < 16; j++) {
        int k = kk * 16 + j;
        float p = s[j];
        const float4* vr = Vs4 + k * 32 + h * 8;
        #pragma unroll
        for (int d4 = 0; d4 < 8; d4++) {
            float4 vv = vr[d4 ^ h];
            o[d4 * 4 + 0] += p * vv.x; o[d4 * 4 + 1] += p * vv.y;
            o[d4 * 4 + 2] += p * vv.z; o[d4 * 4 + 3] += p * vv.w;
        }
    }

    float stot = ssum + __shfl_xor_sync(0xffffffffu, ssum, 1);
    float inv = 1.f / stot;

    float od[16];
    #pragma unroll
    for (int j = 0; j < 16; j++) {
        float t0 = o[j]      + __shfl_xor_sync(0xffffffffu, o[j],      1);
        float t1 = o[j + 16] + __shfl_xor_sync(0xffffffffu, o[j + 16], 1);
        od[j] = (kk ? t1 : t0) * inv;
    }
    // store tf32 bits: consumed raw by the output GEMM
    float4* xo = (float4*)(x + ((size_t)(b * NPIX + n)) * CDIM + hh * 128 + h * HD + kk * 16);
    #pragma unroll
    for (int d4 = 0; d4 < 4; d4++) {
        float4 r = {__uint_as_float(f2tf(od[d4 * 4 + 0])), __uint_as_float(f2tf(od[d4 * 4 + 1])),
                    __uint_as_float(f2tf(od[d4 * 4 + 2])), __uint_as_float(f2tf(od[d4 * 4 + 3]))};
        xo[d4] = r;
    }
}

// ---------------- launch ----------------
extern "C" void kernel_launch(void* const* d_in, const int* in_sizes, int n_in,
                              void* d_out, int out_size) {
    const float* qh   = (const float*)d_in[0];
    const float* kh   = (const float*)d_in[1];
    const float* vh   = (const float*)d_in[2];
    const float* cmap = (const float*)d_in[3];
    const float* Wq   = (const float*)d_in[4];
    const float* bq   = (const float*)d_in[5];
    const float* Wk   = (const float*)d_in[6];
    const float* bk   = (const float*)d_in[7];
    const float* Wv   = (const float*)d_in[8];
    const float* bv   = (const float*)d_in[9];
    const float* Wo   = (const float*)d_in[10];
    const float* bo   = (const float*)d_in[11];
    float* out = (float*)d_out;

    float *pq, *pk, *pv, *px;
    uint32_t* pw;
    int* pidx;
    cudaGetSymbolAddress((void**)&pq,   g_q);
    cudaGetSymbolAddress((void**)&pk,   g_k);
    cudaGetSymbolAddress((void**)&pv,   g_v);
    cudaGetSymbolAddress((void**)&px,   g_x);
    cudaGetSymbolAddress((void**)&pw,   g_w);
    cudaGetSymbolAddress((void**)&pidx, g_idx);

    cudaFuncSetAttribute(gemm_tf32<0>, cudaFuncAttributeMaxDynamicSharedMemorySize, GSMEM);
    cudaFuncSetAttribute(gemm_tf32<1>, cudaFuncAttributeMaxDynamicSharedMemorySize, GSMEM);
    cudaFuncSetAttribute(attn_kernel, cudaFuncAttributeMaxDynamicSharedMemorySize, 33024);

    topk_expand_kernel<<<64, 256>>>(cmap, pidx);
    wconv_kernel<<<256, 256>>>(Wq, Wk, Wv, Wo, pw);

    dim3 gp(NPIX / 128, CDIM / 64, 6);
    gemm_tf32<0><<<gp, 256, GSMEM>>>(qh, kh, vh, pw, bq, bk, bv, pq, pk, pv);

    attn_kernel<<<dim3(NLOW, BATCH, 2), 128, 33024>>>(pq, pk, pv, pidx, px);

    dim3 go(CDIM / 128, NPIX / 64, BATCH);
    gemm_tf32<1><<<go, 256, GSMEM>>>(px, nullptr, nullptr, pw,
                                     bo, nullptr, nullptr, out, nullptr, nullptr);
}

// round 9
// speedup vs baseline: 4.0571x; 1.4828x over previous
#include <cuda_runtime.h>
#include <math.h>
#include <stdint.h>

#define NPIX 4096
#define CDIM 256
#define NLOW 256
#define KLEN 32
#define NHEADS 8
#define HD 32
#define BATCH 2

// ---------------- scratch (no allocations allowed) ----------------
__device__ float    g_q[BATCH * NPIX * CDIM];   // tf32 bits (B,N,C)
__device__ float    g_k[BATCH * NPIX * CDIM];   // tf32 bits
__device__ float    g_v[BATCH * NPIX * CDIM];   // tf32 bits
__device__ float    g_x[BATCH * NPIX * CDIM];   // tf32 bits
__device__ uint32_t g_w[4 * CDIM * CDIM];       // Wq,Wk,Wv,Wo as tf32 bits
__device__ int      g_idx[BATCH * NLOW * KLEN];

// ---------------- helpers ----------------
__device__ __forceinline__ uint32_t f2tf(float x) {
    uint32_t r;
    asm("cvt.rna.tf32.f32 %0, %1;" : "=r"(r) : "f"(x));
    return r;
}
__device__ __forceinline__ void mma_tf32(float* c, const uint32_t* a, const uint32_t* b) {
    asm volatile(
        "mma.sync.aligned.m16n8k8.row.col.f32.tf32.tf32.f32 "
        "{%0,%1,%2,%3},{%4,%5,%6,%7},{%8,%9},{%0,%1,%2,%3};"
        : "+f"(c[0]), "+f"(c[1]), "+f"(c[2]), "+f"(c[3])
        : "r"(a[0]), "r"(a[1]), "r"(a[2]), "r"(a[3]), "r"(b[0]), "r"(b[1]));
}
__device__ __forceinline__ void cp16(const void* dst, const void* src) {
    uint32_t d = (uint32_t)__cvta_generic_to_shared(dst);
    asm volatile("cp.async.cg.shared.global [%0], [%1], 16;" :: "r"(d), "l"(src));
}
#define CP_COMMIT() asm volatile("cp.async.commit_group;" ::: "memory")
#define CP_WAIT0()  asm volatile("cp.async.wait_group 0;" ::: "memory")
#define CP_WAIT1()  asm volatile("cp.async.wait_group 1;" ::: "memory")

// ---------------- weight pre-convert: fp32 -> tf32 bits ----------------
__global__ __launch_bounds__(256) void wconv_kernel(const float* __restrict__ Wq,
                                                    const float* __restrict__ Wk,
                                                    const float* __restrict__ Wv,
                                                    const float* __restrict__ Wo,
                                                    uint32_t* __restrict__ gw) {
    int i = blockIdx.x * 256 + threadIdx.x;
    int which = i >> 14;
    int off = (i & 16383) * 4;
    const float* src = (which == 0) ? Wq : (which == 1) ? Wk : (which == 2) ? Wv : Wo;
    float4 v = *(const float4*)&src[off];
    uint4 r = {f2tf(v.x), f2tf(v.y), f2tf(v.z), f2tf(v.w)};
    *(uint4*)&gw[which * 65536 + off] = r;
}

// ---------------- top-2 + index expansion (one warp per row) ----------------
__global__ __launch_bounds__(256) void topk_expand_kernel(const float* __restrict__ cmap,
                                                          int* __restrict__ idx) {
    int lane = threadIdx.x & 31;
    int row  = blockIdx.x * 8 + (threadIdx.x >> 5);
    const float* r = cmap + (size_t)row * NLOW;
    float m1 = -1e30f, m2 = -1e30f;
    int i1 = 0, i2 = 0;
    #pragma unroll
    for (int l = 0; l < 8; l++) {
        int j = l * 32 + lane;
        float v = r[j];
        if (v > m1)      { m2 = m1; i2 = i1; m1 = v; i1 = j; }
        else if (v > m2) { m2 = v;  i2 = j; }
    }
    #pragma unroll
    for (int off = 16; off > 0; off >>= 1) {
        float om1 = __shfl_xor_sync(0xffffffffu, m1, off);
        float om2 = __shfl_xor_sync(0xffffffffu, m2, off);
        int   oi1 = __shfl_xor_sync(0xffffffffu, i1, off);
        int   oi2 = __shfl_xor_sync(0xffffffffu, i2, off);
        if (om1 > m1) {
            if (m1 > om2) { m2 = m1; i2 = i1; } else { m2 = om2; i2 = oi2; }
            m1 = om1; i1 = oi1;
        } else if (om1 > m2) { m2 = om1; i2 = oi1; }
    }
    int t   = (lane < 16) ? i1 : i2;
    int pos = lane & 15;
    int r0  = (t >> 4) << 2;
    int c0  = (t & 15) << 2;
    idx[(size_t)row * KLEN + lane] = (r0 + (pos >> 2)) * 64 + c0 + (pos & 3);
}

// ---------------- tf32 GEMM: 128x64 CTA tile, CVT-free mainloop ----------------
// MODE 0 writes tf32 BITS (consumed by tensor-core attention); MODE 1 writes fp32.
#define AW 136
#define A_WORDS (32 * AW)
#define B_WORDS 2304
#define STW (A_WORDS + B_WORDS)
#define GSMEM (2 * STW * 4)

template<int MODE>
__global__ __launch_bounds__(256) void gemm_tf32(
    const float* __restrict__ Aq, const float* __restrict__ Ak, const float* __restrict__ Av,
    const uint32_t* __restrict__ gw,
    const float* __restrict__ bq, const float* __restrict__ bk, const float* __restrict__ bv,
    float* __restrict__ oq, float* __restrict__ ok2, float* __restrict__ ov) {
    extern __shared__ uint32_t sw[];
    int m0 = blockIdx.x * 128;
    int c0 = blockIdx.y * 64;
    int t    = threadIdx.x;
    int lane = t & 31, w = t >> 5;
    int wm = w & 3, wc = w >> 2;
    int g = lane >> 2, tq = lane & 3;

    const float* PA;
    const uint32_t* PB;
    const float* bias;
    float* outp;  size_t OS;

    if (MODE == 0) {
        int which = blockIdx.z >> 1, b = blockIdx.z & 1;
        const float* Ain = (which == 0) ? Aq : (which == 1) ? Ak : Av;
        PA   = Ain + (size_t)b * CDIM * NPIX;
        PB   = gw + (size_t)which * 65536;
        bias = (which == 0) ? bq : (which == 1) ? bk : bv;
        float* Out = (which == 0) ? oq : (which == 1) ? ok2 : ov;
        outp = Out + (size_t)b * NPIX * CDIM;  OS = CDIM;
    } else {
        int b = blockIdx.z;
        PA   = (const float*)(gw + 3 * 65536);
        PB   = (const uint32_t*)(Aq + (size_t)b * NPIX * CDIM);
        bias = bq;
        outp = oq + (size_t)b * CDIM * NPIX;  OS = NPIX;
    }

    float accx[2][4][4];
    #pragma unroll
    for (int ms = 0; ms < 2; ms++)
        #pragma unroll
        for (int cs = 0; cs < 4; cs++)
            #pragma unroll
            for (int r = 0; r < 4; r++) accx[ms][cs][r] = 0.f;

    float4 pa[4];

    auto ldgA = [&](int kb) {
        #pragma unroll
        for (int p = 0; p < 4; p++) {
            int idx = p * 256 + t;
            int k = idx >> 5, m4 = idx & 31;
            pa[p] = *(const float4*)&PA[(size_t)(kb + k) * NPIX + m0 + m4 * 4];
        }
    };
    auto stsA = [&](int s) {
        uint32_t* A_ = sw + s * STW;
        #pragma unroll
        for (int p = 0; p < 4; p++) {
            int idx = p * 256 + t;
            int k = idx >> 5, m4 = idx & 31;
            uint4 v = {f2tf(pa[p].x), f2tf(pa[p].y), f2tf(pa[p].z), f2tf(pa[p].w)};
            *(uint4*)&A_[k * AW + m4 * 4] = v;
        }
    };
    auto cpStage = [&](int s, int kb) {
        uint32_t* A_ = sw + s * STW;
        uint32_t* B_ = A_ + A_WORDS;
        if (MODE == 1) {
            #pragma unroll
            for (int p = 0; p < 4; p++) {
                int idx = p * 256 + t;
                int k = idx >> 5, m4 = idx & 31;
                cp16(&A_[k * AW + m4 * 4], &PA[(size_t)(kb + k) * CDIM + m0 + m4 * 4]);
            }
            #pragma unroll
            for (int p = 0; p < 2; p++) {
                int idx = p * 256 + t;
                int n = idx >> 3, k4 = idx & 7;
                cp16(&B_[n * 36 + k4 * 4], &PB[(size_t)(c0 + n) * CDIM + kb + k4 * 4]);
            }
        } else {
            #pragma unroll
            for (int p = 0; p < 2; p++) {
                int idx = p * 256 + t;
                int k = idx >> 4, n4 = idx & 15;
                cp16(&B_[k * 72 + n4 * 4], &PB[(size_t)(kb + k) * CDIM + c0 + n4 * 4]);
            }
        }
    };

    if (MODE == 0) ldgA(0);
    cpStage(0, 0); CP_COMMIT();
    if (MODE == 0) stsA(0);

    int s = 0;
    for (int c = 0; c < 8; c++, s ^= 1) {
        CP_WAIT0();
        __syncthreads();
        bool more = (c < 7);
        if (more) {
            if (MODE == 0) ldgA((c + 1) * 32);
            cpStage(s ^ 1, (c + 1) * 32);
            CP_COMMIT();
        }

        uint32_t* A_ = sw + s * STW;
        uint32_t* B_ = A_ + A_WORDS;
        #pragma unroll
        for (int kk = 0; kk < 32; kk += 8) {
            uint32_t a[2][4], bb[4][2];
            #pragma unroll
            for (int ms = 0; ms < 2; ms++) {
                int bm = wm * 32 + ms * 16;
                a[ms][0] = A_[(kk + tq) * AW + bm + g];
                a[ms][1] = A_[(kk + tq) * AW + bm + g + 8];
                a[ms][2] = A_[(kk + 4 + tq) * AW + bm + g];
                a[ms][3] = A_[(kk + 4 + tq) * AW + bm + g + 8];
            }
            #pragma unroll
            for (int cs = 0; cs < 4; cs++) {
                int bc = wc * 32 + cs * 8;
                if (MODE == 0) {
                    bb[cs][0] = B_[(kk + tq) * 72 + bc + g];
                    bb[cs][1] = B_[(kk + 4 + tq) * 72 + bc + g];
                } else {
                    bb[cs][0] = B_[(bc + g) * 36 + kk + tq];
                    bb[cs][1] = B_[(bc + g) * 36 + kk + 4 + tq];
                }
            }
            #pragma unroll
            for (int ms = 0; ms < 2; ms++)
                #pragma unroll
                for (int cs = 0; cs < 4; cs++)
                    mma_tf32(accx[ms][cs], a[ms], bb[cs]);
        }
        if (more && MODE == 0) stsA(s ^ 1);
    }

    #pragma unroll
    for (int ms = 0; ms < 2; ms++) {
        int mb = m0 + wm * 32 + ms * 16;
        int r0 = mb + g, r1 = mb + g + 8;
        #pragma unroll
        for (int cs = 0; cs < 4; cs++) {
            int c = c0 + wc * 32 + cs * 8 + tq * 2;
            if (MODE == 0) {
                // store tf32 bits for the attention mma
                float2 b2 = *(const float2*)&bias[c];
                uint2 v0 = {f2tf(accx[ms][cs][0] + b2.x), f2tf(accx[ms][cs][1] + b2.y)};
                uint2 v1 = {f2tf(accx[ms][cs][2] + b2.x), f2tf(accx[ms][cs][3] + b2.y)};
                *(uint2*)&outp[(size_t)r0 * OS + c] = v0;
                *(uint2*)&outp[(size_t)r1 * OS + c] = v1;
            } else {
                float br0 = bias[r0], br1 = bias[r1];
                float2 v0 = {accx[ms][cs][0] + br0, accx[ms][cs][1] + br0};
                float2 v1 = {accx[ms][cs][2] + br1, accx[ms][cs][3] + br1};
                *(float2*)&outp[(size_t)r0 * OS + c] = v0;
                *(float2*)&outp[(size_t)r1 * OS + c] = v1;
            }
        }
    }
}

// ---------------- tensor-core block sparse attention ----------------
// CTA = (qlow, b, hh); 4 warps = 4 heads of this half. Per warp:
//   S[16q x 32k] = Q·K^T via 16 mma(m16n8k8 tf32), softmax on c-frags,
//   P staged in smem (tf32), O[16q x 32d] = P·V via 16 mma.
// K/V/Q hold tf32 bits (written by the proj GEMM). Tiles padded to stride 132/36
// so all fragment LDS are bank-conflict-free (V b-frag 2-way max).
#define KVW 132
#define ASMEM ((32 * KVW * 2 + 16 * KVW + 4 * 16 * 36) * 4)   // 51456 B

__global__ __launch_bounds__(128) void attn_kernel(const float* __restrict__ qproj,
                                                   const float* __restrict__ kproj,
                                                   const float* __restrict__ vproj,
                                                   const int* __restrict__ idx,
                                                   float* __restrict__ x) {
    int qlow = blockIdx.x;
    int b    = blockIdx.y;
    int hh   = blockIdx.z;
    extern __shared__ uint32_t smu[];
    uint32_t* Ks = smu;                    // [32][132]
    uint32_t* Vs = Ks + 32 * KVW;          // [32][132]
    uint32_t* Qs = Vs + 32 * KVW;          // [16][132]
    uint32_t* Ps = Qs + 16 * KVW;          // [4][16*36]
    __shared__ int sidx[KLEN];
    int t = threadIdx.x;
    int lane = t & 31, w = t >> 5;
    if (t < KLEN) sidx[t] = idx[((size_t)b * NLOW + qlow) * KLEN + t];
    __syncthreads();

    const float* kb = kproj + (size_t)b * NPIX * CDIM + hh * 128;
    const float* vb = vproj + (size_t)b * NPIX * CDIM + hh * 128;
    const float* qb = qproj + ((size_t)b * NPIX + qlow * 16) * CDIM + hh * 128;

    // group 1: Q + K
    #pragma unroll
    for (int p = 0; p < 4; p++) {
        int li = p * 128 + t;              // 0..511
        int r = li >> 5, c4 = li & 31;
        cp16(&Qs[r * KVW + c4 * 4], &qb[(size_t)r * CDIM + c4 * 4]);
    }
    #pragma unroll
    for (int p = 0; p < 8; p++) {
        int li = p * 128 + t;              // 0..1023
        int r = li >> 5, c4 = li & 31;
        cp16(&Ks[r * KVW + c4 * 4], &kb[(size_t)sidx[r] * CDIM + c4 * 4]);
    }
    CP_COMMIT();
    // group 2: V
    #pragma unroll
    for (int p = 0; p < 8; p++) {
        int li = p * 128 + t;
        int r = li >> 5, c4 = li & 31;
        cp16(&Vs[r * KVW + c4 * 4], &vb[(size_t)sidx[r] * CDIM + c4 * 4]);
    }
    CP_COMMIT();

    int g = lane >> 2, tq = lane & 3;
    int hc = w * 32;                       // this warp's head column base

    CP_WAIT1();            // Q + K resident (V in flight)
    __syncthreads();

    // Q fragments
    uint32_t aq[4][4];
    #pragma unroll
    for (int ks = 0; ks < 4; ks++) {
        aq[ks][0] = Qs[g * KVW + hc + ks * 8 + tq];
        aq[ks][1] = Qs[(g + 8) * KVW + hc + ks * 8 + tq];
        aq[ks][2] = Qs[g * KVW + hc + ks * 8 + tq + 4];
        aq[ks][3] = Qs[(g + 8) * KVW + hc + ks * 8 + tq + 4];
    }

    // S = Q @ K^T
    float sc[4][4];
    #pragma unroll
    for (int nt = 0; nt < 4; nt++)
        #pragma unroll
        for (int r = 0; r < 4; r++) sc[nt][r] = 0.f;
    #pragma unroll
    for (int nt = 0; nt < 4; nt++) {
        #pragma unroll
        for (int ks = 0; ks < 4; ks++) {
            uint32_t bK[2];
            bK[0] = Ks[(nt * 8 + g) * KVW + hc + ks * 8 + tq];
            bK[1] = Ks[(nt * 8 + g) * KVW + hc + ks * 8 + tq + 4];
            mma_tf32(sc[nt], aq[ks], bK);
        }
    }

    // softmax (rows g and g+8; reduce over the tq quad)
    const float scale = 0.17677669529663687f;   // 32^-0.5
    float mx0 = -1e30f, mx1 = -1e30f;
    #pragma unroll
    for (int nt = 0; nt < 4; nt++) {
        #pragma unroll
        for (int r = 0; r < 4; r++) sc[nt][r] *= scale;
        mx0 = fmaxf(mx0, fmaxf(sc[nt][0], sc[nt][1]));
        mx1 = fmaxf(mx1, fmaxf(sc[nt][2], sc[nt][3]));
    }
    #pragma unroll
    for (int o = 1; o <= 2; o <<= 1) {
        mx0 = fmaxf(mx0, __shfl_xor_sync(0xffffffffu, mx0, o));
        mx1 = fmaxf(mx1, __shfl_xor_sync(0xffffffffu, mx1, o));
    }
    float sum0 = 0.f, sum1 = 0.f;
    #pragma unroll
    for (int nt = 0; nt < 4; nt++) {
        sc[nt][0] = __expf(sc[nt][0] - mx0);
        sc[nt][1] = __expf(sc[nt][1] - mx0);
        sc[nt][2] = __expf(sc[nt][2] - mx1);
        sc[nt][3] = __expf(sc[nt][3] - mx1);
        sum0 += sc[nt][0] + sc[nt][1];
        sum1 += sc[nt][2] + sc[nt][3];
    }
    #pragma unroll
    for (int o = 1; o <= 2; o <<= 1) {
        sum0 += __shfl_xor_sync(0xffffffffu, sum0, o);
        sum1 += __shfl_xor_sync(0xffffffffu, sum1, o);
    }

    // stage P (tf32 bits) for the PV mma
    uint32_t* Pw = Ps + w * (16 * 36);
    #pragma unroll
    for (int nt = 0; nt < 4; nt++) {
        Pw[g * 36 + nt * 8 + 2 * tq]           = f2tf(sc[nt][0]);
        Pw[g * 36 + nt * 8 + 2 * tq + 1]       = f2tf(sc[nt][1]);
        Pw[(g + 8) * 36 + nt * 8 + 2 * tq]     = f2tf(sc[nt][2]);
        Pw[(g + 8) * 36 + nt * 8 + 2 * tq + 1] = f2tf(sc[nt][3]);
    }
    __syncwarp();

    CP_WAIT0();            // V resident
    __syncthreads();

    // O = P @ V
    float oc[4][4];
    #pragma unroll
    for (int nt = 0; nt < 4; nt++)
        #pragma unroll
        for (int r = 0; r < 4; r++) oc[nt][r] = 0.f;
    #pragma unroll
    for (int ks = 0; ks < 4; ks++) {
        uint32_t ap[4];
        ap[0] = Pw[g * 36 + ks * 8 + tq];
        ap[1] = Pw[(g + 8) * 36 + ks * 8 + tq];
        ap[2] = Pw[g * 36 + ks * 8 + tq + 4];
        ap[3] = Pw[(g + 8) * 36 + ks * 8 + tq + 4];
        #pragma unroll
        for (int nt = 0; nt < 4; nt++) {
            uint32_t bV[2];
            bV[0] = Vs[(ks * 8 + tq) * KVW + hc + nt * 8 + g];
            bV[1] = Vs[(ks * 8 + tq + 4) * KVW + hc + nt * 8 + g];
            mma_tf32(oc[nt], ap, bV);
        }
    }

    // normalize + store tf32 bits to x
    float inv0 = 1.f / sum0, inv1 = 1.f / sum1;
    int n0 = qlow * 16 + g;
    float* x0 = x + ((size_t)b * NPIX + n0) * CDIM + hh * 128 + hc;
    float* x1 = x0 + 8 * CDIM;
    #pragma unroll
    for (int nt = 0; nt < 4; nt++) {
        int col = nt * 8 + 2 * tq;
        uint2 u0 = {f2tf(oc[nt][0] * inv0), f2tf(oc[nt][1] * inv0)};
        uint2 u1 = {f2tf(oc[nt][2] * inv1), f2tf(oc[nt][3] * inv1)};
        *(uint2*)&x0[col] = u0;
        *(uint2*)&x1[col] = u1;
    }
}

// ---------------- launch ----------------
extern "C" void kernel_launch(void* const* d_in, const int* in_sizes, int n_in,
                              void* d_out, int out_size) {
    const float* qh   = (const float*)d_in[0];
    const float* kh   = (const float*)d_in[1];
    const float* vh   = (const float*)d_in[2];
    const float* cmap = (const float*)d_in[3];
    const float* Wq   = (const float*)d_in[4];
    const float* bq   = (const float*)d_in[5];
    const float* Wk   = (const float*)d_in[6];
    const float* bk   = (const float*)d_in[7];
    const float* Wv   = (const float*)d_in[8];
    const float* bv   = (const float*)d_in[9];
    const float* Wo   = (const float*)d_in[10];
    const float* bo   = (const float*)d_in[11];
    float* out = (float*)d_out;

    float *pq, *pk, *pv, *px;
    uint32_t* pw;
    int* pidx;
    cudaGetSymbolAddress((void**)&pq,   g_q);
    cudaGetSymbolAddress((void**)&pk,   g_k);
    cudaGetSymbolAddress((void**)&pv,   g_v);
    cudaGetSymbolAddress((void**)&px,   g_x);
    cudaGetSymbolAddress((void**)&pw,   g_w);
    cudaGetSymbolAddress((void**)&pidx, g_idx);

    cudaFuncSetAttribute(gemm_tf32<0>, cudaFuncAttributeMaxDynamicSharedMemorySize, GSMEM);
    cudaFuncSetAttribute(gemm_tf32<1>, cudaFuncAttributeMaxDynamicSharedMemorySize, GSMEM);
    cudaFuncSetAttribute(attn_kernel, cudaFuncAttributeMaxDynamicSharedMemorySize, ASMEM);

    topk_expand_kernel<<<64, 256>>>(cmap, pidx);
    wconv_kernel<<<256, 256>>>(Wq, Wk, Wv, Wo, pw);

    dim3 gp(NPIX / 128, CDIM / 64, 6);
    gemm_tf32<0><<<gp, 256, GSMEM>>>(qh, kh, vh, pw, bq, bk, bv, pq, pk, pv);

    attn_kernel<<<dim3(NLOW, BATCH, 2), 128, ASMEM>>>(pq, pk, pv, pidx, px);

    dim3 go(CDIM / 128, NPIX / 64, BATCH);
    gemm_tf32<1><<<go, 256, GSMEM>>>(px, nullptr, nullptr, pw,
                                     bo, nullptr, nullptr, out, nullptr, nullptr);
}

// round 10
// speedup vs baseline: 4.6923x; 1.1565x over previous
#include <cuda_runtime.h>
#include <math.h>
#include <stdint.h>

#define NPIX 4096
#define CDIM 256
#define NLOW 256
#define KLEN 32
#define NHEADS 8
#define HD 32
#define BATCH 2

// ---------------- scratch (no allocations allowed) ----------------
__device__ float    g_q[BATCH * NPIX * CDIM];   // tf32 bits (B,N,C)
__device__ float    g_k[BATCH * NPIX * CDIM];   // tf32 bits
__device__ float    g_v[BATCH * NPIX * CDIM];   // tf32 bits
__device__ float    g_x[BATCH * NPIX * CDIM];   // tf32 bits
__device__ uint32_t g_w[4 * CDIM * CDIM];       // Wq,Wk,Wv,Wo as tf32 bits
__device__ int      g_idx[BATCH * NLOW * KLEN];

// ---------------- helpers ----------------
__device__ __forceinline__ uint32_t f2tf(float x) {
    uint32_t r;
    asm("cvt.rna.tf32.f32 %0, %1;" : "=r"(r) : "f"(x));
    return r;
}
__device__ __forceinline__ void mma_tf32(float* c, const uint32_t* a, const uint32_t* b) {
    asm volatile(
        "mma.sync.aligned.m16n8k8.row.col.f32.tf32.tf32.f32 "
        "{%0,%1,%2,%3},{%4,%5,%6,%7},{%8,%9},{%0,%1,%2,%3};"
        : "+f"(c[0]), "+f"(c[1]), "+f"(c[2]), "+f"(c[3])
        : "r"(a[0]), "r"(a[1]), "r"(a[2]), "r"(a[3]), "r"(b[0]), "r"(b[1]));
}
__device__ __forceinline__ void cp16(const void* dst, const void* src) {
    uint32_t d = (uint32_t)__cvta_generic_to_shared(dst);
    asm volatile("cp.async.cg.shared.global [%0], [%1], 16;" :: "r"(d), "l"(src));
}
#define CP_COMMIT() asm volatile("cp.async.commit_group;" ::: "memory")
#define CP_WAIT0()  asm volatile("cp.async.wait_group 0;" ::: "memory")
#define CP_WAIT1()  asm volatile("cp.async.wait_group 1;" ::: "memory")

// ---------------- prep: top-2 expand (blocks 0..63) + weight convert (64..319) ----------------
__global__ __launch_bounds__(256) void prep_kernel(const float* __restrict__ cmap,
                                                   int* __restrict__ idx,
                                                   const float* __restrict__ Wq,
                                                   const float* __restrict__ Wk,
                                                   const float* __restrict__ Wv,
                                                   const float* __restrict__ Wo,
                                                   uint32_t* __restrict__ gw) {
    if (blockIdx.x < 64) {
        int lane = threadIdx.x & 31;
        int row  = blockIdx.x * 8 + (threadIdx.x >> 5);
        const float* r = cmap + (size_t)row * NLOW;
        float m1 = -1e30f, m2 = -1e30f;
        int i1 = 0, i2 = 0;
        #pragma unroll
        for (int l = 0; l < 8; l++) {
            int j = l * 32 + lane;
            float v = r[j];
            if (v > m1)      { m2 = m1; i2 = i1; m1 = v; i1 = j; }
            else if (v > m2) { m2 = v;  i2 = j; }
        }
        #pragma unroll
        for (int off = 16; off > 0; off >>= 1) {
            float om1 = __shfl_xor_sync(0xffffffffu, m1, off);
            float om2 = __shfl_xor_sync(0xffffffffu, m2, off);
            int   oi1 = __shfl_xor_sync(0xffffffffu, i1, off);
            int   oi2 = __shfl_xor_sync(0xffffffffu, i2, off);
            if (om1 > m1) {
                if (m1 > om2) { m2 = m1; i2 = i1; } else { m2 = om2; i2 = oi2; }
                m1 = om1; i1 = oi1;
            } else if (om1 > m2) { m2 = om1; i2 = oi1; }
        }
        int t   = (lane < 16) ? i1 : i2;
        int pos = lane & 15;
        int r0  = (t >> 4) << 2;
        int c0  = (t & 15) << 2;
        idx[(size_t)row * KLEN + lane] = (r0 + (pos >> 2)) * 64 + c0 + (pos & 3);
    } else {
        int i = (blockIdx.x - 64) * 256 + threadIdx.x;
        int which = i >> 14;
        int off = (i & 16383) * 4;
        const float* src = (which == 0) ? Wq : (which == 1) ? Wk : (which == 2) ? Wv : Wo;
        float4 v = *(const float4*)&src[off];
        uint4 r = {f2tf(v.x), f2tf(v.y), f2tf(v.z), f2tf(v.w)};
        *(uint4*)&gw[which * 65536 + off] = r;
    }
}

// ---------------- proj GEMM: 128x128 CTA tile, tf32-bit output ----------------
// grid (32, 2, 6 = which*2+b); 8 warps = 4(m)x2(n), warp tile 32m x 64n.
// A (C,NPIX) fp32 staged LDG->cvt->STS; B = g_w tf32 via cp.async; out (NPIX,C) tf32 bits.
#define AW 136
#define PSTW (2 * 32 * AW)          // words per stage (A + B)
#define PGSM (2 * PSTW * 4)         // 69632 B

__global__ __launch_bounds__(256) void gemm_proj(
    const float* __restrict__ Aq, const float* __restrict__ Ak, const float* __restrict__ Av,
    const uint32_t* __restrict__ gw,
    const float* __restrict__ bq, const float* __restrict__ bk, const float* __restrict__ bv,
    float* __restrict__ oq, float* __restrict__ ok2, float* __restrict__ ov) {
    extern __shared__ uint32_t sw[];
    int m0 = blockIdx.x * 128;
    int c0 = blockIdx.y * 128;
    int t    = threadIdx.x;
    int lane = t & 31, w = t >> 5;
    int wm = w & 3, wc = w >> 2;     // wm: 32m, wc: 64n
    int g = lane >> 2, tq = lane & 3;

    int which = blockIdx.z >> 1, b = blockIdx.z & 1;
    const float* Ain = (which == 0) ? Aq : (which == 1) ? Ak : Av;
    const float* PA = Ain + (size_t)b * CDIM * NPIX;
    const uint32_t* PB = gw + (size_t)which * 65536;
    const float* bias = (which == 0) ? bq : (which == 1) ? bk : bv;
    float* Out = (which == 0) ? oq : (which == 1) ? ok2 : ov;
    float* outp = Out + (size_t)b * NPIX * CDIM;

    float acc[2][8][4];
    #pragma unroll
    for (int ms = 0; ms < 2; ms++)
        #pragma unroll
        for (int cs = 0; cs < 8; cs++)
            #pragma unroll
            for (int r = 0; r < 4; r++) acc[ms][cs][r] = 0.f;

    float4 pa[4];
    auto ldgA = [&](int kb) {
        #pragma unroll
        for (int p = 0; p < 4; p++) {
            int idx = p * 256 + t;
            int k = idx >> 5, m4 = idx & 31;
            pa[p] = *(const float4*)&PA[(size_t)(kb + k) * NPIX + m0 + m4 * 4];
        }
    };
    auto stsA = [&](int s) {
        uint32_t* A_ = sw + s * PSTW;
        #pragma unroll
        for (int p = 0; p < 4; p++) {
            int idx = p * 256 + t;
            int k = idx >> 5, m4 = idx & 31;
            uint4 v = {f2tf(pa[p].x), f2tf(pa[p].y), f2tf(pa[p].z), f2tf(pa[p].w)};
            *(uint4*)&A_[k * AW + m4 * 4] = v;
        }
    };
    auto cpB = [&](int s, int kb) {
        uint32_t* B_ = sw + s * PSTW + 32 * AW;
        #pragma unroll
        for (int p = 0; p < 4; p++) {
            int idx = p * 256 + t;
            int k = idx >> 5, n4 = idx & 31;
            cp16(&B_[k * AW + n4 * 4], &PB[(size_t)(kb + k) * CDIM + c0 + n4 * 4]);
        }
    };

    ldgA(0);
    cpB(0, 0); CP_COMMIT();
    stsA(0);

    int s = 0;
    for (int c = 0; c < 8; c++, s ^= 1) {
        CP_WAIT0();
        __syncthreads();
        bool more = (c < 7);
        if (more) {
            ldgA((c + 1) * 32);
            cpB(s ^ 1, (c + 1) * 32);
            CP_COMMIT();
        }

        uint32_t* A_ = sw + s * PSTW;
        uint32_t* B_ = A_ + 32 * AW;
        #pragma unroll
        for (int kk = 0; kk < 32; kk += 8) {
            uint32_t a[2][4], bb[8][2];
            #pragma unroll
            for (int ms = 0; ms < 2; ms++) {
                int bm = wm * 32 + ms * 16;
                a[ms][0] = A_[(kk + tq) * AW + bm + g];
                a[ms][1] = A_[(kk + tq) * AW + bm + g + 8];
                a[ms][2] = A_[(kk + 4 + tq) * AW + bm + g];
                a[ms][3] = A_[(kk + 4 + tq) * AW + bm + g + 8];
            }
            #pragma unroll
            for (int cs = 0; cs < 8; cs++) {
                int bc = wc * 64 + cs * 8;
                bb[cs][0] = B_[(kk + tq) * AW + bc + g];
                bb[cs][1] = B_[(kk + 4 + tq) * AW + bc + g];
            }
            #pragma unroll
            for (int ms = 0; ms < 2; ms++)
                #pragma unroll
                for (int cs = 0; cs < 8; cs++)
                    mma_tf32(acc[ms][cs], a[ms], bb[cs]);
        }
        if (more) stsA(s ^ 1);
    }

    #pragma unroll
    for (int ms = 0; ms < 2; ms++) {
        int mb = m0 + wm * 32 + ms * 16;
        int r0 = mb + g, r1 = mb + g + 8;
        #pragma unroll
        for (int cs = 0; cs < 8; cs++) {
            int c = c0 + wc * 64 + cs * 8 + tq * 2;
            float2 b2 = *(const float2*)&bias[c];
            uint2 v0 = {f2tf(acc[ms][cs][0] + b2.x), f2tf(acc[ms][cs][1] + b2.y)};
            uint2 v1 = {f2tf(acc[ms][cs][2] + b2.x), f2tf(acc[ms][cs][3] + b2.y)};
            *(uint2*)&outp[(size_t)r0 * CDIM + c] = v0;
            *(uint2*)&outp[(size_t)r1 * CDIM + c] = v1;
        }
    }
}

// ---------------- output GEMM: 128x64 CTA tile (fp32 out, transposed) ----------------
#define O_AW 136
#define O_AWORDS (32 * O_AW)
#define O_BWORDS 2304
#define OSTW (O_AWORDS + O_BWORDS)
#define OGSM (2 * OSTW * 4)

__global__ __launch_bounds__(256) void gemm_out(
    const float* __restrict__ x, const uint32_t* __restrict__ gw,
    const float* __restrict__ bo, float* __restrict__ out) {
    extern __shared__ uint32_t sw[];
    int m0 = blockIdx.x * 128;    // cout block
    int c0 = blockIdx.y * 64;     // pixel block
    int t    = threadIdx.x;
    int lane = t & 31, w = t >> 5;
    int wm = w & 3, wc = w >> 2;
    int g = lane >> 2, tq = lane & 3;

    int b = blockIdx.z;
    const float* PA = (const float*)(gw + 3 * 65536);            // Wo tf32
    const uint32_t* PB = (const uint32_t*)(x + (size_t)b * NPIX * CDIM);
    float* outp = out + (size_t)b * CDIM * NPIX;

    float accx[2][4][4];
    #pragma unroll
    for (int ms = 0; ms < 2; ms++)
        #pragma unroll
        for (int cs = 0; cs < 4; cs++)
            #pragma unroll
            for (int r = 0; r < 4; r++) accx[ms][cs][r] = 0.f;

    auto cpStage = [&](int s, int kb) {
        uint32_t* A_ = sw + s * OSTW;
        uint32_t* B_ = A_ + O_AWORDS;
        #pragma unroll
        for (int p = 0; p < 4; p++) {
            int idx = p * 256 + t;
            int k = idx >> 5, m4 = idx & 31;
            cp16(&A_[k * O_AW + m4 * 4], &PA[(size_t)(kb + k) * CDIM + m0 + m4 * 4]);
        }
        #pragma unroll
        for (int p = 0; p < 2; p++) {
            int idx = p * 256 + t;
            int n = idx >> 3, k4 = idx & 7;
            cp16(&B_[n * 36 + k4 * 4], &PB[(size_t)(c0 + n) * CDIM + kb + k4 * 4]);
        }
    };

    cpStage(0, 0); CP_COMMIT();

    int s = 0;
    for (int c = 0; c < 8; c++, s ^= 1) {
        CP_WAIT0();
        __syncthreads();
        bool more = (c < 7);
        if (more) { cpStage(s ^ 1, (c + 1) * 32); CP_COMMIT(); }

        uint32_t* A_ = sw + s * OSTW;
        uint32_t* B_ = A_ + O_AWORDS;
        #pragma unroll
        for (int kk = 0; kk < 32; kk += 8) {
            uint32_t a[2][4], bb[4][2];
            #pragma unroll
            for (int ms = 0; ms < 2; ms++) {
                int bm = wm * 32 + ms * 16;
                a[ms][0] = A_[(kk + tq) * O_AW + bm + g];
                a[ms][1] = A_[(kk + tq) * O_AW + bm + g + 8];
                a[ms][2] = A_[(kk + 4 + tq) * O_AW + bm + g];
                a[ms][3] = A_[(kk + 4 + tq) * O_AW + bm + g + 8];
            }
            #pragma unroll
            for (int cs = 0; cs < 4; cs++) {
                int bc = wc * 32 + cs * 8;
                bb[cs][0] = B_[(bc + g) * 36 + kk + tq];
                bb[cs][1] = B_[(bc + g) * 36 + kk + 4 + tq];
            }
            #pragma unroll
            for (int ms = 0; ms < 2; ms++)
                #pragma unroll
                for (int cs = 0; cs < 4; cs++)
                    mma_tf32(accx[ms][cs], a[ms], bb[cs]);
        }
    }

    #pragma unroll
    for (int ms = 0; ms < 2; ms++) {
        int mb = m0 + wm * 32 + ms * 16;
        int r0 = mb + g, r1 = mb + g + 8;
        #pragma unroll
        for (int cs = 0; cs < 4; cs++) {
            int c = c0 + wc * 32 + cs * 8 + tq * 2;
            float br0 = bo[r0], br1 = bo[r1];
            float2 v0 = {accx[ms][cs][0] + br0, accx[ms][cs][1] + br0};
            float2 v1 = {accx[ms][cs][2] + br1, accx[ms][cs][3] + br1};
            *(float2*)&outp[(size_t)r0 * NPIX + c] = v0;
            *(float2*)&outp[(size_t)r1 * NPIX + c] = v1;
        }
    }
}

// ---------------- tensor-core block sparse attention (QP-union smem) ----------------
#define KVW 132
#define QPW 2304                                   // max(16*132, 4*16*36)
#define ASMEM ((32 * KVW * 2 + QPW) * 4)           // 43008 B

__global__ __launch_bounds__(128) void attn_kernel(const float* __restrict__ qproj,
                                                   const float* __restrict__ kproj,
                                                   const float* __restrict__ vproj,
                                                   const int* __restrict__ idx,
                                                   float* __restrict__ x) {
    int qlow = blockIdx.x;
    int b    = blockIdx.y;
    int hh   = blockIdx.z;
    extern __shared__ uint32_t smu[];
    uint32_t* Ks = smu;                    // [32][132]
    uint32_t* Vs = Ks + 32 * KVW;          // [32][132]
    uint32_t* QP = Vs + 32 * KVW;          // Q [16][132] then P [4][16*36]
    __shared__ int sidx[KLEN];
    int t = threadIdx.x;
    int lane = t & 31, w = t >> 5;
    if (t < KLEN) sidx[t] = idx[((size_t)b * NLOW + qlow) * KLEN + t];
    __syncthreads();

    const float* kb = kproj + (size_t)b * NPIX * CDIM + hh * 128;
    const float* vb = vproj + (size_t)b * NPIX * CDIM + hh * 128;
    const float* qb = qproj + ((size_t)b * NPIX + qlow * 16) * CDIM + hh * 128;

    // group 1: Q + K
    #pragma unroll
    for (int p = 0; p < 4; p++) {
        int li = p * 128 + t;              // 0..511
        int r = li >> 5, c4 = li & 31;
        cp16(&QP[r * KVW + c4 * 4], &qb[(size_t)r * CDIM + c4 * 4]);
    }
    #pragma unroll
    for (int p = 0; p < 8; p++) {
        int li = p * 128 + t;              // 0..1023
        int r = li >> 5, c4 = li & 31;
        cp16(&Ks[r * KVW + c4 * 4], &kb[(size_t)sidx[r] * CDIM + c4 * 4]);
    }
    CP_COMMIT();
    // group 2: V
    #pragma unroll
    for (int p = 0; p < 8; p++) {
        int li = p * 128 + t;
        int r = li >> 5, c4 = li & 31;
        cp16(&Vs[r * KVW + c4 * 4], &vb[(size_t)sidx[r] * CDIM + c4 * 4]);
    }
    CP_COMMIT();

    int g = lane >> 2, tq = lane & 3;
    int hc = w * 32;

    CP_WAIT1();            // Q + K resident (V in flight)
    __syncthreads();

    // Q fragments
    uint32_t aq[4][4];
    #pragma unroll
    for (int ks = 0; ks < 4; ks++) {
        aq[ks][0] = QP[g * KVW + hc + ks * 8 + tq];
        aq[ks][1] = QP[(g + 8) * KVW + hc + ks * 8 + tq];
        aq[ks][2] = QP[g * KVW + hc + ks * 8 + tq + 4];
        aq[ks][3] = QP[(g + 8) * KVW + hc + ks * 8 + tq + 4];
    }

    // S = Q @ K^T
    float sc[4][4];
    #pragma unroll
    for (int nt = 0; nt < 4; nt++)
        #pragma unroll
        for (int r = 0; r < 4; r++) sc[nt][r] = 0.f;
    #pragma unroll
    for (int nt = 0; nt < 4; nt++) {
        #pragma unroll
        for (int ks = 0; ks < 4; ks++) {
            uint32_t bK[2];
            bK[0] = Ks[(nt * 8 + g) * KVW + hc + ks * 8 + tq];
            bK[1] = Ks[(nt * 8 + g) * KVW + hc + ks * 8 + tq + 4];
            mma_tf32(sc[nt], aq[ks], bK);
        }
    }

    // softmax
    const float scale = 0.17677669529663687f;
    float mx0 = -1e30f, mx1 = -1e30f;
    #pragma unroll
    for (int nt = 0; nt < 4; nt++) {
        #pragma unroll
        for (int r = 0; r < 4; r++) sc[nt][r] *= scale;
        mx0 = fmaxf(mx0, fmaxf(sc[nt][0], sc[nt][1]));
        mx1 = fmaxf(mx1, fmaxf(sc[nt][2], sc[nt][3]));
    }
    #pragma unroll
    for (int o = 1; o <= 2; o <<= 1) {
        mx0 = fmaxf(mx0, __shfl_xor_sync(0xffffffffu, mx0, o));
        mx1 = fmaxf(mx1, __shfl_xor_sync(0xffffffffu, mx1, o));
    }
    float sum0 = 0.f, sum1 = 0.f;
    #pragma unroll
    for (int nt = 0; nt < 4; nt++) {
        sc[nt][0] = __expf(sc[nt][0] - mx0);
        sc[nt][1] = __expf(sc[nt][1] - mx0);
        sc[nt][2] = __expf(sc[nt][2] - mx1);
        sc[nt][3] = __expf(sc[nt][3] - mx1);
        sum0 += sc[nt][0] + sc[nt][1];
        sum1 += sc[nt][2] + sc[nt][3];
    }
    #pragma unroll
    for (int o = 1; o <= 2; o <<= 1) {
        sum0 += __shfl_xor_sync(0xffffffffu, sum0, o);
        sum1 += __shfl_xor_sync(0xffffffffu, sum1, o);
    }

    __syncthreads();       // all warps done reading Q region before P overwrites it

    // stage P (tf32 bits) in the QP union region
    uint32_t* Pw = QP + w * (16 * 36);
    #pragma unroll
    for (int nt = 0; nt < 4; nt++) {
        Pw[g * 36 + nt * 8 + 2 * tq]           = f2tf(sc[nt][0]);
        Pw[g * 36 + nt * 8 + 2 * tq + 1]       = f2tf(sc[nt][1]);
        Pw[(g + 8) * 36 + nt * 8 + 2 * tq]     = f2tf(sc[nt][2]);
        Pw[(g + 8) * 36 + nt * 8 + 2 * tq + 1] = f2tf(sc[nt][3]);
    }

    CP_WAIT0();            // V resident
    __syncthreads();

    // O = P @ V
    float oc[4][4];
    #pragma unroll
    for (int nt = 0; nt < 4; nt++)
        #pragma unroll
        for (int r = 0; r < 4; r++) oc[nt][r] = 0.f;
    #pragma unroll
    for (int ks = 0; ks < 4; ks++) {
        uint32_t ap[4];
        ap[0] = Pw[g * 36 + ks * 8 + tq];
        ap[1] = Pw[(g + 8) * 36 + ks * 8 + tq];
        ap[2] = Pw[g * 36 + ks * 8 + tq + 4];
        ap[3] = Pw[(g + 8) * 36 + ks * 8 + tq + 4];
        #pragma unroll
        for (int nt = 0; nt < 4; nt++) {
            uint32_t bV[2];
            bV[0] = Vs[(ks * 8 + tq) * KVW + hc + nt * 8 + g];
            bV[1] = Vs[(ks * 8 + tq + 4) * KVW + hc + nt * 8 + g];
            mma_tf32(oc[nt], ap, bV);
        }
    }

    // normalize + store tf32 bits to x
    float inv0 = 1.f / sum0, inv1 = 1.f / sum1;
    int n0 = qlow * 16 + g;
    float* x0 = x + ((size_t)b * NPIX + n0) * CDIM + hh * 128 + hc;
    float* x1 = x0 + 8 * CDIM;
    #pragma unroll
    for (int nt = 0; nt < 4; nt++) {
        int col = nt * 8 + 2 * tq;
        uint2 u0 = {f2tf(oc[nt][0] * inv0), f2tf(oc[nt][1] * inv0)};
        uint2 u1 = {f2tf(oc[nt][2] * inv1), f2tf(oc[nt][3] * inv1)};
        *(uint2*)&x0[col] = u0;
        *(uint2*)&x1[col] = u1;
    }
}

// ---------------- launch ----------------
extern "C" void kernel_launch(void* const* d_in, const int* in_sizes, int n_in,
                              void* d_out, int out_size) {
    const float* qh   = (const float*)d_in[0];
    const float* kh   = (const float*)d_in[1];
    const float* vh   = (const float*)d_in[2];
    const float* cmap = (const float*)d_in[3];
    const float* Wq   = (const float*)d_in[4];
    const float* bq   = (const float*)d_in[5];
    const float* Wk   = (const float*)d_in[6];
    const float* bk   = (const float*)d_in[7];
    const float* Wv   = (const float*)d_in[8];
    const float* bv   = (const float*)d_in[9];
    const float* Wo   = (const float*)d_in[10];
    const float* bo   = (const float*)d_in[11];
    float* out = (float*)d_out;

    float *pq, *pk, *pv, *px;
    uint32_t* pw;
    int* pidx;
    cudaGetSymbolAddress((void**)&pq,   g_q);
    cudaGetSymbolAddress((void**)&pk,   g_k);
    cudaGetSymbolAddress((void**)&pv,   g_v);
    cudaGetSymbolAddress((void**)&px,   g_x);
    cudaGetSymbolAddress((void**)&pw,   g_w);
    cudaGetSymbolAddress((void**)&pidx, g_idx);

    cudaFuncSetAttribute(gemm_proj, cudaFuncAttributeMaxDynamicSharedMemorySize, PGSM);
    cudaFuncSetAttribute(gemm_out, cudaFuncAttributeMaxDynamicSharedMemorySize, OGSM);
    cudaFuncSetAttribute(attn_kernel, cudaFuncAttributeMaxDynamicSharedMemorySize, ASMEM);

    prep_kernel<<<320, 256>>>(cmap, pidx, Wq, Wk, Wv, Wo, pw);

    dim3 gp(NPIX / 128, CDIM / 128, 6);
    gemm_proj<<<gp, 256, PGSM>>>(qh, kh, vh, pw, bq, bk, bv, pq, pk, pv);

    attn_kernel<<<dim3(NLOW, BATCH, 2), 128, ASMEM>>>(pq, pk, pv, pidx, px);

    dim3 go(CDIM / 128, NPIX / 64, BATCH);
    gemm_out<<<go, 256, OGSM>>>(px, pw, bo, out);
}

// round 11
// speedup vs baseline: 4.9085x; 1.0461x over previous
#include <cuda_runtime.h>
#include <math.h>
#include <stdint.h>

#define NPIX 4096
#define CDIM 256
#define NLOW 256
#define KLEN 32
#define BATCH 2
#define CW 128              // words (half2) per channel row

// ---------------- scratch (no allocations allowed) ----------------
__device__ float    g_q[BATCH * NPIX * CDIM];   // half2 words (only half used)
__device__ float    g_k[BATCH * NPIX * CDIM];
__device__ float    g_v[BATCH * NPIX * CDIM];
__device__ float    g_x[BATCH * NPIX * CDIM];
__device__ uint32_t g_w[4 * CDIM * CDIM / 2];   // W^T as half2: [which][cout][k/2]
__device__ int      g_idx[BATCH * NLOW * KLEN];

// ---------------- helpers ----------------
__device__ __forceinline__ uint32_t pk2(float lo, float hi) {   // half2: lo in lower
    uint32_t r;
    asm("cvt.rn.f16x2.f32 %0, %1, %2;" : "=r"(r) : "f"(hi), "f"(lo));
    return r;
}
__device__ __forceinline__ uint32_t prmt(uint32_t a, uint32_t b, uint32_t sel) {
    uint32_t r;
    asm("prmt.b32 %0, %1, %2, %3;" : "=r"(r) : "r"(a), "r"(b), "r"(sel));
    return r;
}
__device__ __forceinline__ void mma_f16(float* c, const uint32_t* a, const uint32_t* b) {
    asm volatile(
        "mma.sync.aligned.m16n8k16.row.col.f32.f16.f16.f32 "
        "{%0,%1,%2,%3},{%4,%5,%6,%7},{%8,%9},{%0,%1,%2,%3};"
        : "+f"(c[0]), "+f"(c[1]), "+f"(c[2]), "+f"(c[3])
        : "r"(a[0]), "r"(a[1]), "r"(a[2]), "r"(a[3]), "r"(b[0]), "r"(b[1]));
}
__device__ __forceinline__ void cp16(const void* dst, const void* src) {
    uint32_t d = (uint32_t)__cvta_generic_to_shared(dst);
    asm volatile("cp.async.cg.shared.global [%0], [%1], 16;" :: "r"(d), "l"(src));
}
#define CP_COMMIT() asm volatile("cp.async.commit_group;" ::: "memory")
#define CP_WAIT0()  asm volatile("cp.async.wait_group 0;" ::: "memory")
#define CP_WAIT1()  asm volatile("cp.async.wait_group 1;" ::: "memory")

// ---------------- prep: topk (blocks 0..63) + weight transpose->half2 (64..191) ----------------
// Wt layout: [which][cout][kp]  (kp = k/2, half2 lo = even k)
__global__ __launch_bounds__(256) void prep_kernel(const float* __restrict__ cmap,
                                                   int* __restrict__ idx,
                                                   const float* __restrict__ Wq,
                                                   const float* __restrict__ Wk,
                                                   const float* __restrict__ Wv,
                                                   const float* __restrict__ Wo,
                                                   uint32_t* __restrict__ wt) {
    __shared__ float sm[64][33];
    int t = threadIdx.x;
    if (blockIdx.x < 64) {
        int lane = t & 31;
        int row  = blockIdx.x * 8 + (t >> 5);
        const float* r = cmap + (size_t)row * NLOW;
        float m1 = -1e30f, m2 = -1e30f;
        int i1 = 0, i2 = 0;
        #pragma unroll
        for (int l = 0; l < 8; l++) {
            int j = l * 32 + lane;
            float v = r[j];
            if (v > m1)      { m2 = m1; i2 = i1; m1 = v; i1 = j; }
            else if (v > m2) { m2 = v;  i2 = j; }
        }
        #pragma unroll
        for (int off = 16; off > 0; off >>= 1) {
            float om1 = __shfl_xor_sync(0xffffffffu, m1, off);
            float om2 = __shfl_xor_sync(0xffffffffu, m2, off);
            int   oi1 = __shfl_xor_sync(0xffffffffu, i1, off);
            int   oi2 = __shfl_xor_sync(0xffffffffu, i2, off);
            if (om1 > m1) {
                if (m1 > om2) { m2 = m1; i2 = i1; } else { m2 = om2; i2 = oi2; }
                m1 = om1; i1 = oi1;
            } else if (om1 > m2) { m2 = om1; i2 = oi1; }
        }
        int tk  = (lane < 16) ? i1 : i2;
        int pos = lane & 15;
        int r0  = (tk >> 4) << 2;
        int c0  = (tk & 15) << 2;
        idx[(size_t)row * KLEN + lane] = (r0 + (pos >> 2)) * 64 + c0 + (pos & 3);
    } else {
        int bi = blockIdx.x - 64;              // 0..127
        int which = bi >> 5;
        int tile  = bi & 31;
        int c0 = (tile >> 2) * 32;             // cout tile
        int k0 = (tile & 3) * 64;              // k tile (64 k = 32 kp)
        const float* W = (which == 0) ? Wq : (which == 1) ? Wk : (which == 2) ? Wv : Wo;
        #pragma unroll
        for (int p = 0; p < 8; p++) {
            int i = p * 256 + t;               // 2048 floats
            int row = i >> 5, c = i & 31;
            sm[row][c] = W[(size_t)(k0 + row) * CDIM + c0 + c];
        }
        __syncthreads();
        #pragma unroll
        for (int p = 0; p < 4; p++) {
            int i = p * 256 + t;               // 1024 words
            int cc = i >> 5, kp = i & 31;
            wt[(size_t)which * 32768 + (size_t)(c0 + cc) * CW + (k0 >> 1) + kp] =
                pk2(sm[2 * kp][cc], sm[2 * kp + 1][cc]);
        }
    }
}

// ---------------- fp16 QKV projection: CTA 128pix x 128cout ----------------
// out[pix][cout] half2 words. A (C,NPIX) fp32 staged cvt->STS; B = Wt cp.async.
// 8 warps = 4(m)x2(n); warp tile 32m x 64n; K-chunk 32 (16 kp), pitch 20.
#define P_AW 20
#define P_STW (128 * P_AW * 2)      // 5120 words per stage
#define P_GSM (2 * P_STW * 4)       // 40960 B

__global__ __launch_bounds__(256) void gemm_proj(
    const float* __restrict__ Aq, const float* __restrict__ Ak, const float* __restrict__ Av,
    const uint32_t* __restrict__ wt,
    const float* __restrict__ bq, const float* __restrict__ bk, const float* __restrict__ bv,
    uint32_t* __restrict__ oq, uint32_t* __restrict__ ok2, uint32_t* __restrict__ ov) {
    extern __shared__ uint32_t sw[];
    int m0 = blockIdx.x * 128;                 // pixels
    int c0 = blockIdx.y * 128;                 // couts
    int t = threadIdx.x;
    int lane = t & 31, w = t >> 5;
    int wm = w & 3, wc = w >> 2;
    int g = lane >> 2, tq = lane & 3;

    int which = blockIdx.z >> 1, b = blockIdx.z & 1;
    const float* Ain = (which == 0) ? Aq : (which == 1) ? Ak : Av;
    const float* PA = Ain + (size_t)b * CDIM * NPIX;
    const uint32_t* PB = wt + (size_t)which * 32768;
    const float* bias = (which == 0) ? bq : (which == 1) ? bk : bv;
    uint32_t* Out = (which == 0) ? oq : (which == 1) ? ok2 : ov;
    uint32_t* outp = Out + (size_t)b * NPIX * CW;

    float acc[2][8][4];
    #pragma unroll
    for (int ms = 0; ms < 2; ms++)
        #pragma unroll
        for (int cs = 0; cs < 8; cs++)
            #pragma unroll
            for (int r = 0; r < 4; r++) acc[ms][cs][r] = 0.f;

    int mg = t >> 3;                           // 0..31 (4 pixels each)
    float4 pa[2][2];
    auto ldgA = [&](int kb) {
        #pragma unroll
        for (int p = 0; p < 2; p++) {
            int kp = (t & 7) + 8 * p;
            pa[p][0] = *(const float4*)&PA[(size_t)(kb + 2 * kp) * NPIX + m0 + mg * 4];
            pa[p][1] = *(const float4*)&PA[(size_t)(kb + 2 * kp + 1) * NPIX + m0 + mg * 4];
        }
    };
    auto stsA = [&](int s) {
        uint32_t* A_ = sw + s * P_STW;
        #pragma unroll
        for (int p = 0; p < 2; p++) {
            int kp = (t & 7) + 8 * p;
            const float* lo = (const float*)&pa[p][0];
            const float* hi = (const float*)&pa[p][1];
            #pragma unroll
            for (int i = 0; i < 4; i++)
                A_[(mg * 4 + i) * P_AW + kp] = pk2(lo[i], hi[i]);
        }
    };
    auto cpB = [&](int s, int kb) {
        uint32_t* B_ = sw + s * P_STW + 128 * P_AW;
        #pragma unroll
        for (int p = 0; p < 2; p++) {
            int idx = p * 256 + t;
            int n = idx >> 2, q = idx & 3;
            cp16(&B_[n * P_AW + q * 4], &PB[(size_t)(c0 + n) * CW + (kb >> 1) + q * 4]);
        }
    };

    ldgA(0);
    cpB(0, 0); CP_COMMIT();
    stsA(0);

    int s = 0;
    for (int c = 0; c < 8; c++, s ^= 1) {
        CP_WAIT0();
        __syncthreads();
        bool more = (c < 7);
        if (more) {
            ldgA((c + 1) * 32);
            cpB(s ^ 1, (c + 1) * 32);
            CP_COMMIT();
        }
        uint32_t* A_ = sw + s * P_STW;
        uint32_t* B_ = A_ + 128 * P_AW;
        #pragma unroll
        for (int kc = 0; kc < 2; kc++) {
            uint32_t a[2][4], bb[8][2];
            #pragma unroll
            for (int ms = 0; ms < 2; ms++) {
                int base = (wm * 32 + ms * 16 + g) * P_AW + kc * 8 + tq;
                a[ms][0] = A_[base];
                a[ms][1] = A_[base + 8 * P_AW];
                a[ms][2] = A_[base + 4];
                a[ms][3] = A_[base + 8 * P_AW + 4];
            }
            #pragma unroll
            for (int cs = 0; cs < 8; cs++) {
                int bbase = (wc * 64 + cs * 8 + g) * P_AW + kc * 8 + tq;
                bb[cs][0] = B_[bbase];
                bb[cs][1] = B_[bbase + 4];
            }
            #pragma unroll
            for (int ms = 0; ms < 2; ms++)
                #pragma unroll
                for (int cs = 0; cs < 8; cs++)
                    mma_f16(acc[ms][cs], a[ms], bb[cs]);
        }
        if (more) stsA(s ^ 1);
    }

    // epilogue: half2 words, c-contiguous
    #pragma unroll
    for (int ms = 0; ms < 2; ms++) {
        int r0 = m0 + wm * 32 + ms * 16 + g;
        int r1 = r0 + 8;
        #pragma unroll
        for (int cs = 0; cs < 8; cs++) {
            int c = c0 + wc * 64 + cs * 8 + 2 * tq;
            float2 b2 = *(const float2*)&bias[c];
            outp[(size_t)r0 * CW + (c >> 1)] = pk2(acc[ms][cs][0] + b2.x, acc[ms][cs][1] + b2.y);
            outp[(size_t)r1 * CW + (c >> 1)] = pk2(acc[ms][cs][2] + b2.x, acc[ms][cs][3] + b2.y);
        }
    }
}

// ---------------- fp16 output GEMM: CTA 64cout x 128pix, fp32 transposed out ----------------
#define O_STW (64 * P_AW + 128 * P_AW)   // 3840 words per stage
#define O_GSM (2 * O_STW * 4)            // 30720 B

__global__ __launch_bounds__(256) void gemm_out(
    const uint32_t* __restrict__ xw, const uint32_t* __restrict__ wt,
    const float* __restrict__ bo, float* __restrict__ out) {
    extern __shared__ uint32_t sw[];
    int m0 = blockIdx.x * 64;                  // couts
    int n0 = blockIdx.y * 128;                 // pixels
    int t = threadIdx.x;
    int lane = t & 31, w = t >> 5;
    int wm = w & 1, wc = w >> 1;
    int g = lane >> 2, tq = lane & 3;

    int b = blockIdx.z;
    const uint32_t* PA = wt + 3 * 32768;                 // Wo^T [cout][kp]
    const uint32_t* PB = xw + (size_t)b * NPIX * CW;     // x [pix][kp]
    float* outp = out + (size_t)b * CDIM * NPIX;

    float acc[2][4][4];
    #pragma unroll
    for (int ms = 0; ms < 2; ms++)
        #pragma unroll
        for (int cs = 0; cs < 4; cs++)
            #pragma unroll
            for (int r = 0; r < 4; r++) acc[ms][cs][r] = 0.f;

    auto cpStage = [&](int s, int kb) {
        uint32_t* A_ = sw + s * O_STW;
        uint32_t* B_ = A_ + 64 * P_AW;
        {
            int n = t >> 2, q = t & 3;         // 256 cp16 for A
            cp16(&A_[n * P_AW + q * 4], &PA[(size_t)(m0 + n) * CW + (kb >> 1) + q * 4]);
        }
        #pragma unroll
        for (int p = 0; p < 2; p++) {
            int idx = p * 256 + t;
            int n = idx >> 2, q = idx & 3;
            cp16(&B_[n * P_AW + q * 4], &PB[(size_t)(n0 + n) * CW + (kb >> 1) + q * 4]);
        }
    };

    cpStage(0, 0); CP_COMMIT();

    int s = 0;
    for (int c = 0; c < 8; c++, s ^= 1) {
        CP_WAIT0();
        __syncthreads();
        bool more = (c < 7);
        if (more) { cpStage(s ^ 1, (c + 1) * 32); CP_COMMIT(); }

        uint32_t* A_ = sw + s * O_STW;
        uint32_t* B_ = A_ + 64 * P_AW;
        #pragma unroll
        for (int kc = 0; kc < 2; kc++) {
            uint32_t a[2][4], bb[4][2];
            #pragma unroll
            for (int ms = 0; ms < 2; ms++) {
                int base = (wm * 32 + ms * 16 + g) * P_AW + kc * 8 + tq;
                a[ms][0] = A_[base];
                a[ms][1] = A_[base + 8 * P_AW];
                a[ms][2] = A_[base + 4];
                a[ms][3] = A_[base + 8 * P_AW + 4];
            }
            #pragma unroll
            for (int cs = 0; cs < 4; cs++) {
                int bbase = (wc * 32 + cs * 8 + g) * P_AW + kc * 8 + tq;
                bb[cs][0] = B_[bbase];
                bb[cs][1] = B_[bbase + 4];
            }
            #pragma unroll
            for (int ms = 0; ms < 2; ms++)
                #pragma unroll
                for (int cs = 0; cs < 4; cs++)
                    mma_f16(acc[ms][cs], a[ms], bb[cs]);
        }
    }

    #pragma unroll
    for (int ms = 0; ms < 2; ms++) {
        int r0 = m0 + wm * 32 + ms * 16 + g;
        int r1 = r0 + 8;
        float b0v = bo[r0], b1v = bo[r1];
        #pragma unroll
        for (int cs = 0; cs < 4; cs++) {
            int c = n0 + wc * 32 + cs * 8 + 2 * tq;
            float2 v0 = {acc[ms][cs][0] + b0v, acc[ms][cs][1] + b0v};
            float2 v1 = {acc[ms][cs][2] + b1v, acc[ms][cs][3] + b1v};
            *(float2*)&outp[(size_t)r0 * NPIX + c] = v0;
            *(float2*)&outp[(size_t)r1 * NPIX + c] = v1;
        }
    }
}

// ---------------- fp16 tensor-core sparse attention ----------------
// CTA = (qlow, b, hh); 4 warps = 4 heads. K rows are natural B operands for QK.
// V transposed in-smem (prmt) for PV. Pitch 68 (rows) / 20 (Vt,P): conflict-free frags.
#define AKW 68
#define A_KS 0
#define A_VR (32 * AKW)            // 2176
#define A_QS (A_VR + 32 * AKW)     // 4352
#define A_VT (A_QS + 16 * AKW)     // 5440
#define A_PS (A_VT + 128 * 20)     // 8000
#define A_SM ((A_PS + 4 * 320) * 4)   // 37120 B

__global__ __launch_bounds__(128) void attn_kernel(const uint32_t* __restrict__ qw,
                                                   const uint32_t* __restrict__ kw,
                                                   const uint32_t* __restrict__ vw,
                                                   const int* __restrict__ idx,
                                                   uint32_t* __restrict__ xw) {
    int qlow = blockIdx.x;
    int b    = blockIdx.y;
    int hh   = blockIdx.z;
    extern __shared__ uint32_t smu[];
    uint32_t* Ks = smu + A_KS;
    uint32_t* Vr = smu + A_VR;
    uint32_t* Qs = smu + A_QS;
    uint32_t* Vt = smu + A_VT;
    uint32_t* Ps = smu + A_PS;
    __shared__ int sidx[KLEN];
    int t = threadIdx.x;
    int lane = t & 31, w = t >> 5;
    if (t < KLEN) sidx[t] = idx[((size_t)b * NLOW + qlow) * KLEN + t];
    __syncthreads();

    size_t bN = (size_t)b * NPIX;
    int hho = hh * 64;                          // word offset of this half

    // group 1: Q (16 rows) + K (32 rows)
    #pragma unroll
    for (int p = 0; p < 2; p++) {
        int li = p * 128 + t;                   // 0..255
        int r = li >> 4, q4 = li & 15;
        cp16(&Qs[r * AKW + q4 * 4], &qw[(bN + qlow * 16 + r) * CW + hho + q4 * 4]);
    }
    #pragma unroll
    for (int p = 0; p < 4; p++) {
        int li = p * 128 + t;                   // 0..511
        int r = li >> 4, q4 = li & 15;
        cp16(&Ks[r * AKW + q4 * 4], &kw[(bN + sidx[r]) * CW + hho + q4 * 4]);
    }
    CP_COMMIT();
    // group 2: V
    #pragma unroll
    for (int p = 0; p < 4; p++) {
        int li = p * 128 + t;
        int r = li >> 4, q4 = li & 15;
        cp16(&Vr[r * AKW + q4 * 4], &vw[(bN + sidx[r]) * CW + hho + q4 * 4]);
    }
    CP_COMMIT();

    int g = lane >> 2, tq = lane & 3;
    int hw = w * 16;                            // head word offset within 64

    CP_WAIT1();
    __syncthreads();

    // Q fragments (2 k-steps over d=32)
    uint32_t aq[2][4];
    #pragma unroll
    for (int kc = 0; kc < 2; kc++) {
        int base = g * AKW + hw + kc * 8 + tq;
        aq[kc][0] = Qs[base];
        aq[kc][1] = Qs[base + 8 * AKW];
        aq[kc][2] = Qs[base + 4];
        aq[kc][3] = Qs[base + 8 * AKW + 4];
    }

    // S = Q @ K^T
    float sc[4][4];
    #pragma unroll
    for (int nt = 0; nt < 4; nt++)
        #pragma unroll
        for (int r = 0; r < 4; r++) sc[nt][r] = 0.f;
    #pragma unroll
    for (int nt = 0; nt < 4; nt++) {
        #pragma unroll
        for (int kc = 0; kc < 2; kc++) {
            uint32_t bK[2];
            int bbase = (nt * 8 + g) * AKW + hw + kc * 8 + tq;
            bK[0] = Ks[bbase];
            bK[1] = Ks[bbase + 4];
            mma_f16(sc[nt], aq[kc], bK);
        }
    }

    // softmax
    const float scale = 0.17677669529663687f;   // 32^-0.5
    float mx0 = -1e30f, mx1 = -1e30f;
    #pragma unroll
    for (int nt = 0; nt < 4; nt++) {
        #pragma unroll
        for (int r = 0; r < 4; r++) sc[nt][r] *= scale;
        mx0 = fmaxf(mx0, fmaxf(sc[nt][0], sc[nt][1]));
        mx1 = fmaxf(mx1, fmaxf(sc[nt][2], sc[nt][3]));
    }
    #pragma unroll
    for (int o = 1; o <= 2; o <<= 1) {
        mx0 = fmaxf(mx0, __shfl_xor_sync(0xffffffffu, mx0, o));
        mx1 = fmaxf(mx1, __shfl_xor_sync(0xffffffffu, mx1, o));
    }
    float sum0 = 0.f, sum1 = 0.f;
    #pragma unroll
    for (int nt = 0; nt < 4; nt++) {
        sc[nt][0] = __expf(sc[nt][0] - mx0);
        sc[nt][1] = __expf(sc[nt][1] - mx0);
        sc[nt][2] = __expf(sc[nt][2] - mx1);
        sc[nt][3] = __expf(sc[nt][3] - mx1);
        sum0 += sc[nt][0] + sc[nt][1];
        sum1 += sc[nt][2] + sc[nt][3];
    }
    #pragma unroll
    for (int o = 1; o <= 2; o <<= 1) {
        sum0 += __shfl_xor_sync(0xffffffffu, sum0, o);
        sum1 += __shfl_xor_sync(0xffffffffu, sum1, o);
    }

    CP_WAIT0();
    __syncthreads();        // V raw visible to all

    // transpose V: Vr[key][d-word] -> Vt[d][key-pair], half2 lo = even key
    #pragma unroll
    for (int p = 0; p < 16; p++) {
        int li = p * 128 + t;                   // 0..2047
        int d = li & 127, kp = li >> 7;
        uint32_t w0 = Vr[(2 * kp) * AKW + (d >> 1)];
        uint32_t w1 = Vr[(2 * kp + 1) * AKW + (d >> 1)];
        uint32_t sel = (d & 1) ? 0x7632u : 0x5410u;
        Vt[d * 20 + kp] = prmt(w0, w1, sel);
    }

    // stage P (per-warp region): word (q row, key-pair)
    uint32_t* Pw = Ps + w * 320;
    #pragma unroll
    for (int nt = 0; nt < 4; nt++) {
        Pw[g * 20 + nt * 4 + tq]       = pk2(sc[nt][0], sc[nt][1]);
        Pw[(g + 8) * 20 + nt * 4 + tq] = pk2(sc[nt][2], sc[nt][3]);
    }
    __syncthreads();        // Vt (cross-warp) + P visible

    // O = P @ V
    float oc[4][4];
    #pragma unroll
    for (int nt = 0; nt < 4; nt++)
        #pragma unroll
        for (int r = 0; r < 4; r++) oc[nt][r] = 0.f;
    int hd = w * 32;                            // head d-offset within 128
    #pragma unroll
    for (int kc = 0; kc < 2; kc++) {
        uint32_t ap[4];
        ap[0] = Pw[g * 20 + kc * 8 + tq];
        ap[1] = Pw[(g + 8) * 20 + kc * 8 + tq];
        ap[2] = Pw[g * 20 + kc * 8 + tq + 4];
        ap[3] = Pw[(g + 8) * 20 + kc * 8 + tq + 4];
        #pragma unroll
        for (int nt = 0; nt < 4; nt++) {
            uint32_t bV[2];
            int bbase = (hd + nt * 8 + g) * 20 + kc * 8 + tq;
            bV[0] = Vt[bbase];
            bV[1] = Vt[bbase + 4];
            mma_f16(oc[nt], ap, bV);
        }
    }

    // normalize + store half2 words to x
    float inv0 = 1.f / sum0, inv1 = 1.f / sum1;
    uint32_t* x0 = xw + (bN + qlow * 16 + g) * CW + hho + hw;
    uint32_t* x1 = x0 + 8 * CW;
    #pragma unroll
    for (int nt = 0; nt < 4; nt++) {
        x0[nt * 4 + tq] = pk2(oc[nt][0] * inv0, oc[nt][1] * inv0);
        x1[nt * 4 + tq] = pk2(oc[nt][2] * inv1, oc[nt][3] * inv1);
    }
}

// ---------------- launch ----------------
extern "C" void kernel_launch(void* const* d_in, const int* in_sizes, int n_in,
                              void* d_out, int out_size) {
    const float* qh   = (const float*)d_in[0];
    const float* kh   = (const float*)d_in[1];
    const float* vh   = (const float*)d_in[2];
    const float* cmap = (const float*)d_in[3];
    const float* Wq   = (const float*)d_in[4];
    const float* bq   = (const float*)d_in[5];
    const float* Wk   = (const float*)d_in[6];
    const float* bk   = (const float*)d_in[7];
    const float* Wv   = (const float*)d_in[8];
    const float* bv   = (const float*)d_in[9];
    const float* Wo   = (const float*)d_in[10];
    const float* bo   = (const float*)d_in[11];
    float* out = (float*)d_out;

    uint32_t *pq, *pk, *pv, *px, *pw;
    int* pidx;
    cudaGetSymbolAddress((void**)&pq,   g_q);
    cudaGetSymbolAddress((void**)&pk,   g_k);
    cudaGetSymbolAddress((void**)&pv,   g_v);
    cudaGetSymbolAddress((void**)&px,   g_x);
    cudaGetSymbolAddress((void**)&pw,   g_w);
    cudaGetSymbolAddress((void**)&pidx, g_idx);

    cudaFuncSetAttribute(gemm_proj, cudaFuncAttributeMaxDynamicSharedMemorySize, P_GSM);
    cudaFuncSetAttribute(gemm_out, cudaFuncAttributeMaxDynamicSharedMemorySize, O_GSM);
    cudaFuncSetAttribute(attn_kernel, cudaFuncAttributeMaxDynamicSharedMemorySize, A_SM);

    prep_kernel<<<192, 256>>>(cmap, pidx, Wq, Wk, Wv, Wo, pw);

    dim3 gp(NPIX / 128, CDIM / 128, 6);
    gemm_proj<<<gp, 256, P_GSM>>>(qh, kh, vh, pw, bq, bk, bv, pq, pk, pv);

    attn_kernel<<<dim3(NLOW, BATCH, 2), 128, A_SM>>>(pq, pk, pv, pidx, px);

    dim3 go(CDIM / 64, NPIX / 128, BATCH);
    gemm_out<<<go, 256, O_GSM>>>(px, pw, bo, out);
}